// round 1
// baseline (speedup 1.0000x reference)
#include <cuda_runtime.h>
#include <math.h>

#define Dm   512
#define Hh   8
#define DK   64
#define DFFm 2048
#define Lm   4
#define Bb   2
#define Sm   1024
#define Vv   50257
#define MR   (Bb*Sm)   // 2048 rows

// ---------------- scratch (device globals; no allocs allowed) ----------------
__device__ float g_x  [MR*Dm];
__device__ float g_h  [MR*Dm];
__device__ float g_q  [MR*Dm];
__device__ float g_k  [MR*Dm];
__device__ float g_v  [MR*Dm];
__device__ float g_o  [MR*Dm];
__device__ float g_ffn[MR*DFFm];

// ---------------- embed ----------------
__global__ void embed_kernel(const int* __restrict__ tok,
                             const float* __restrict__ emb,
                             const float* __restrict__ pos,
                             float* __restrict__ x) {
    int idx = blockIdx.x * blockDim.x + threadIdx.x;   // over MR*Dm
    if (idx >= MR*Dm) return;
    int row = idx / Dm, d = idx % Dm;
    int s = row % Sm;
    int t = tok[row];
    x[idx] = emb[t*Dm + d] + pos[s*Dm + d];
}

// ---------------- layernorm (block per row, 128 threads, float4) ----------------
__global__ void __launch_bounds__(128) ln_kernel(const float* __restrict__ x,
                                                 const float* __restrict__ g,
                                                 const float* __restrict__ b,
                                                 float* __restrict__ out) {
    int row = blockIdx.x;
    int t = threadIdx.x;                 // 128 threads * float4 = 512
    const float4 v4 = reinterpret_cast<const float4*>(x + row*Dm)[t];
    __shared__ float red[4];

    float s = v4.x + v4.y + v4.z + v4.w;
    #pragma unroll
    for (int o = 16; o > 0; o >>= 1) s += __shfl_xor_sync(0xffffffffu, s, o);
    if ((t & 31) == 0) red[t >> 5] = s;
    __syncthreads();
    float mean = (red[0] + red[1] + red[2] + red[3]) * (1.0f/Dm);
    __syncthreads();

    float dx = v4.x-mean, dy = v4.y-mean, dz = v4.z-mean, dw = v4.w-mean;
    float ss = dx*dx + dy*dy + dz*dz + dw*dw;
    #pragma unroll
    for (int o = 16; o > 0; o >>= 1) ss += __shfl_xor_sync(0xffffffffu, ss, o);
    if ((t & 31) == 0) red[t >> 5] = ss;
    __syncthreads();
    float var = (red[0] + red[1] + red[2] + red[3]) * (1.0f/Dm);
    float inv = rsqrtf(var + 1e-5f);

    float4 gg = reinterpret_cast<const float4*>(g)[t];
    float4 bb = reinterpret_cast<const float4*>(b)[t];
    float4 o4;
    o4.x = dx*inv*gg.x + bb.x;
    o4.y = dy*inv*gg.y + bb.y;
    o4.z = dz*inv*gg.z + bb.z;
    o4.w = dw*inv*gg.w + bb.w;
    reinterpret_cast<float4*>(out + row*Dm)[t] = o4;
}

// ---------------- GEMM: C[M,N] = act(A[M,K] @ W[N,K]^T + bias[N]) (+ residual) ----------------
// ACT: 0 = none, 1 = exact-erf GELU.  RES: add Rsd[m*N+n].
template<int BM, int BN, int BK, int TM, int TN, int ACT, bool RES>
__global__ void __launch_bounds__((BM/TM)*(BN/TN))
gemm_kernel(const float* __restrict__ A, const float* __restrict__ W,
            const float* __restrict__ bias, const float* __restrict__ Rsd,
            float* __restrict__ C, int Mn, int Nn, int Kn) {
    constexpr int THREADS = (BM/TM)*(BN/TN);
    __shared__ float As[BK][BM+4];
    __shared__ float Bs[BK][BN+4];

    int tid = threadIdx.x;
    int bm = blockIdx.y * BM;
    int bn = blockIdx.x * BN;
    int tn = (tid % (BN/TN)) * TN;
    int tm = (tid / (BN/TN)) * TM;

    float acc[TM][TN];
    #pragma unroll
    for (int i = 0; i < TM; i++)
        #pragma unroll
        for (int j = 0; j < TN; j++) acc[i][j] = 0.f;

    for (int k0 = 0; k0 < Kn; k0 += BK) {
        // A tile: BM x BK (K-major rows), store transposed As[k][m]
        #pragma unroll
        for (int i = tid*4; i < BM*BK; i += THREADS*4) {
            int m = i / BK, kk = i % BK;
            float4 a = *reinterpret_cast<const float4*>(A + (size_t)(bm+m)*Kn + k0 + kk);
            As[kk+0][m] = a.x; As[kk+1][m] = a.y; As[kk+2][m] = a.z; As[kk+3][m] = a.w;
        }
        // W tile: BN x BK (K-major rows), store Bs[k][n]; guard n for ragged N (head)
        #pragma unroll
        for (int i = tid*4; i < BN*BK; i += THREADS*4) {
            int n = i / BK, kk = i % BK;
            int gn = bn + n;
            float4 w = make_float4(0.f,0.f,0.f,0.f);
            if (gn < Nn) w = *reinterpret_cast<const float4*>(W + (size_t)gn*Kn + k0 + kk);
            Bs[kk+0][n] = w.x; Bs[kk+1][n] = w.y; Bs[kk+2][n] = w.z; Bs[kk+3][n] = w.w;
        }
        __syncthreads();

        #pragma unroll
        for (int kk = 0; kk < BK; kk++) {
            float ar[TM], br[TN];
            #pragma unroll
            for (int i = 0; i < TM; i += 4) {
                float4 a4 = *reinterpret_cast<const float4*>(&As[kk][tm+i]);
                ar[i]=a4.x; ar[i+1]=a4.y; ar[i+2]=a4.z; ar[i+3]=a4.w;
            }
            #pragma unroll
            for (int j = 0; j < TN; j += 4) {
                float4 b4 = *reinterpret_cast<const float4*>(&Bs[kk][tn+j]);
                br[j]=b4.x; br[j+1]=b4.y; br[j+2]=b4.z; br[j+3]=b4.w;
            }
            #pragma unroll
            for (int i = 0; i < TM; i++)
                #pragma unroll
                for (int j = 0; j < TN; j++)
                    acc[i][j] += ar[i]*br[j];
        }
        __syncthreads();
    }

    #pragma unroll
    for (int i = 0; i < TM; i++) {
        int m = bm + tm + i;
        #pragma unroll
        for (int j = 0; j < TN; j++) {
            int n = bn + tn + j;
            if (n < Nn) {
                float v = acc[i][j] + bias[n];
                if (ACT == 1) v = 0.5f * v * (1.0f + erff(v * 0.70710678118654752f));
                if (RES) v += Rsd[(size_t)m*Nn + n];
                C[(size_t)m*Nn + n] = v;
            }
        }
    }
}

// ---------------- attention: flash-style fp32, online softmax ----------------
// grid: (S/64 qtiles, B*H); block: 64 threads, one query per thread.
__global__ void __launch_bounds__(64)
attn_kernel(const float* __restrict__ q, const float* __restrict__ k,
            const float* __restrict__ v, float* __restrict__ o) {
    int qt = blockIdx.x;
    int bh = blockIdx.y;
    int b = bh / Hh, h = bh % Hh;
    int t = threadIdx.x;
    int qi = qt*64 + t;
    int rowbase = b * Sm;

    __shared__ float Ks[64][DK];
    __shared__ float Vs[64][DK];

    float qr[DK];
    {
        const float4* qp = reinterpret_cast<const float4*>(q + (size_t)(rowbase+qi)*Dm + h*DK);
        #pragma unroll
        for (int d4 = 0; d4 < DK/4; d4++) {
            float4 x = qp[d4];
            qr[4*d4]=x.x; qr[4*d4+1]=x.y; qr[4*d4+2]=x.z; qr[4*d4+3]=x.w;
        }
    }

    float m = -1e30f, l = 0.f;
    float acc[DK];
    #pragma unroll
    for (int d = 0; d < DK; d++) acc[d] = 0.f;

    for (int kt = 0; kt <= qt; kt++) {
        __syncthreads();
        // cooperative coalesced tile load: 16 threads per key row, 4 rows/iter
        #pragma unroll
        for (int it = 0; it < 16; it++) {
            int r = it*4 + (t >> 4);
            int c = (t & 15) * 4;
            size_t off = (size_t)(rowbase + kt*64 + r)*Dm + h*DK + c;
            *reinterpret_cast<float4*>(&Ks[r][c]) = *reinterpret_cast<const float4*>(k + off);
            *reinterpret_cast<float4*>(&Vs[r][c]) = *reinterpret_cast<const float4*>(v + off);
        }
        __syncthreads();

        int jmax = (kt == qt) ? t : 63;
        for (int j = 0; j <= jmax; j++) {
            // dot with 4 accumulator chains for ILP
            float s0=0.f, s1=0.f, s2=0.f, s3=0.f;
            const float4* kv = reinterpret_cast<const float4*>(Ks[j]);
            #pragma unroll
            for (int d4 = 0; d4 < DK/4; d4++) {
                float4 kk4 = kv[d4];
                s0 += qr[4*d4  ]*kk4.x;
                s1 += qr[4*d4+1]*kk4.y;
                s2 += qr[4*d4+2]*kk4.z;
                s3 += qr[4*d4+3]*kk4.w;
            }
            float s = ((s0+s1)+(s2+s3)) * 0.125f;   // 1/sqrt(64)

            if (s > m) {
                float corr = __expf(m - s);
                l *= corr;
                #pragma unroll
                for (int d = 0; d < DK; d++) acc[d] *= corr;
                m = s;
            }
            float p = __expf(s - m);
            l += p;
            const float4* vv = reinterpret_cast<const float4*>(Vs[j]);
            #pragma unroll
            for (int d4 = 0; d4 < DK/4; d4++) {
                float4 v4 = vv[d4];
                acc[4*d4  ] += p*v4.x;
                acc[4*d4+1] += p*v4.y;
                acc[4*d4+2] += p*v4.z;
                acc[4*d4+3] += p*v4.w;
            }
        }
    }

    float inv = 1.f / l;
    float* op = o + (size_t)(rowbase+qi)*Dm + h*DK;
    #pragma unroll
    for (int d4 = 0; d4 < DK/4; d4++) {
        float4 x;
        x.x = acc[4*d4  ]*inv;
        x.y = acc[4*d4+1]*inv;
        x.z = acc[4*d4+2]*inv;
        x.w = acc[4*d4+3]*inv;
        reinterpret_cast<float4*>(op)[d4] = x;
    }
}

// ---------------- launch ----------------
extern "C" void kernel_launch(void* const* d_in, const int* in_sizes, int n_in,
                              void* d_out, int out_size) {
    const int*   tokens = (const int*)  d_in[0];
    const float* emb    = (const float*)d_in[1];
    const float* pos    = (const float*)d_in[2];
    const float* Wq     = (const float*)d_in[3];
    const float* bq     = (const float*)d_in[4];
    const float* Wk     = (const float*)d_in[5];
    const float* bk     = (const float*)d_in[6];
    const float* Wv     = (const float*)d_in[7];
    const float* bv     = (const float*)d_in[8];
    const float* Wo     = (const float*)d_in[9];
    const float* bo     = (const float*)d_in[10];
    const float* ln1g   = (const float*)d_in[11];
    const float* ln1b   = (const float*)d_in[12];
    const float* W1     = (const float*)d_in[13];
    const float* b1     = (const float*)d_in[14];
    const float* W2     = (const float*)d_in[15];
    const float* b2     = (const float*)d_in[16];
    const float* ln2g   = (const float*)d_in[17];
    const float* ln2b   = (const float*)d_in[18];
    const float* lnfg   = (const float*)d_in[19];
    const float* lnfb   = (const float*)d_in[20];
    const float* Whead  = (const float*)d_in[21];
    const float* bhead  = (const float*)d_in[22];
    float* out = (float*)d_out;

    float *x, *h, *q, *k, *v, *o, *ffn;
    cudaGetSymbolAddress((void**)&x,   g_x);
    cudaGetSymbolAddress((void**)&h,   g_h);
    cudaGetSymbolAddress((void**)&q,   g_q);
    cudaGetSymbolAddress((void**)&k,   g_k);
    cudaGetSymbolAddress((void**)&v,   g_v);
    cudaGetSymbolAddress((void**)&o,   g_o);
    cudaGetSymbolAddress((void**)&ffn, g_ffn);

    embed_kernel<<<(MR*Dm + 255)/256, 256>>>(tokens, emb, pos, x);

    // small-GEMM config: 64x64x16 tiles, 4x4 micro, 256 thr -> grid (8,32) for N=512
    dim3 gsmall(Dm/64, MR/64);
    // FFN1 config: 128x128 tiles -> grid (16,16)
    dim3 gffn1(DFFm/128, MR/128);
    dim3 ghead((Vv + 127)/128, MR/128);
    dim3 gattn(Sm/64, Bb*Hh);

    for (int l = 0; l < Lm; l++) {
        const float* wq = Wq + (size_t)l*Dm*Dm;  const float* biq = bq + l*Dm;
        const float* wk = Wk + (size_t)l*Dm*Dm;  const float* bik = bk + l*Dm;
        const float* wv = Wv + (size_t)l*Dm*Dm;  const float* biv = bv + l*Dm;
        const float* wo = Wo + (size_t)l*Dm*Dm;  const float* bio = bo + l*Dm;
        const float* w1 = W1 + (size_t)l*DFFm*Dm; const float* bi1 = b1 + l*DFFm;
        const float* w2 = W2 + (size_t)l*Dm*DFFm; const float* bi2 = b2 + l*Dm;

        ln_kernel<<<MR, 128>>>(x, ln1g + l*Dm, ln1b + l*Dm, h);
        gemm_kernel<64,64,16,4,4,0,false><<<gsmall,256>>>(h, wq, biq, nullptr, q, MR, Dm, Dm);
        gemm_kernel<64,64,16,4,4,0,false><<<gsmall,256>>>(h, wk, bik, nullptr, k, MR, Dm, Dm);
        gemm_kernel<64,64,16,4,4,0,false><<<gsmall,256>>>(h, wv, biv, nullptr, v, MR, Dm, Dm);
        attn_kernel<<<gattn, 64>>>(q, k, v, o);
        gemm_kernel<64,64,16,4,4,0,true ><<<gsmall,256>>>(o, wo, bio, x, x, MR, Dm, Dm);

        ln_kernel<<<MR, 128>>>(x, ln2g + l*Dm, ln2b + l*Dm, h);
        gemm_kernel<128,128,16,8,8,1,false><<<gffn1,256>>>(h, w1, bi1, nullptr, ffn, MR, DFFm, Dm);
        gemm_kernel<64,64,16,4,4,0,true ><<<gsmall,256>>>(ffn, w2, bi2, x, x, MR, Dm, DFFm);
    }

    ln_kernel<<<MR, 128>>>(x, lnfg, lnfb, h);
    gemm_kernel<128,128,16,8,8,0,false><<<ghead,256>>>(h, Whead, bhead, nullptr, out, MR, Vv, Dm);
}

// round 2
// speedup vs baseline: 1.3796x; 1.3796x over previous
#include <cuda_runtime.h>
#include <cuda_bf16.h>
#include <math.h>

#define Dm   512
#define Hh   8
#define DK   64
#define DFFm 2048
#define Lm   4
#define Bb   2
#define Sm   1024
#define Vv   50257
#define MR   (Bb*Sm)   // 2048 rows

// ---------------- scratch (device globals; no allocs allowed) ----------------
__device__ float g_x[MR*Dm];
__device__ float g_q[MR*Dm];
__device__ float g_k[MR*Dm];
__device__ float g_v[MR*Dm];

__device__ __nv_bfloat16 g_hh[MR*Dm],  g_hl[MR*Dm];     // LN output hi/lo
__device__ __nv_bfloat16 g_oh[MR*Dm],  g_ol[MR*Dm];     // attn output hi/lo
__device__ __nv_bfloat16 g_fh[MR*DFFm], g_fl[MR*DFFm];  // FFN1/GELU output hi/lo

__device__ __nv_bfloat16 g_wqh[Lm*Dm*Dm],   g_wql[Lm*Dm*Dm];
__device__ __nv_bfloat16 g_wkh[Lm*Dm*Dm],   g_wkl[Lm*Dm*Dm];
__device__ __nv_bfloat16 g_wvh[Lm*Dm*Dm],   g_wvl[Lm*Dm*Dm];
__device__ __nv_bfloat16 g_woh[Lm*Dm*Dm],   g_wol[Lm*Dm*Dm];
__device__ __nv_bfloat16 g_w1h[Lm*DFFm*Dm], g_w1l[Lm*DFFm*Dm];
__device__ __nv_bfloat16 g_w2h[Lm*Dm*DFFm], g_w2l[Lm*Dm*DFFm];
__device__ __nv_bfloat16 g_whh[(size_t)Vv*Dm], g_whl[(size_t)Vv*Dm];

// ---------------- helpers ----------------
__device__ __forceinline__ void splitf(float v, __nv_bfloat16& h, __nv_bfloat16& l) {
    h = __float2bfloat16(v);
    l = __float2bfloat16(v - __bfloat162float(h));
}
__device__ __forceinline__ unsigned saddr(const void* p) {
    return (unsigned)__cvta_generic_to_shared(p);
}
__device__ __forceinline__ void ldsm4(unsigned* d, unsigned a) {
    asm volatile("ldmatrix.sync.aligned.m8n8.x4.shared.b16 {%0,%1,%2,%3}, [%4];"
        : "=r"(d[0]), "=r"(d[1]), "=r"(d[2]), "=r"(d[3]) : "r"(a));
}
__device__ __forceinline__ void ldsm2(unsigned* d, unsigned a) {
    asm volatile("ldmatrix.sync.aligned.m8n8.x2.shared.b16 {%0,%1}, [%2];"
        : "=r"(d[0]), "=r"(d[1]) : "r"(a));
}
__device__ __forceinline__ void mma16816(float* c, const unsigned* a, const unsigned* b) {
    asm volatile("mma.sync.aligned.m16n8k16.row.col.f32.bf16.bf16.f32 "
        "{%0,%1,%2,%3}, {%4,%5,%6,%7}, {%8,%9}, {%0,%1,%2,%3};"
        : "+f"(c[0]), "+f"(c[1]), "+f"(c[2]), "+f"(c[3])
        : "r"(a[0]), "r"(a[1]), "r"(a[2]), "r"(a[3]), "r"(b[0]), "r"(b[1]));
}

// ---------------- weight split: fp32 -> bf16 hi/lo ----------------
__global__ void split_kernel(const float* __restrict__ s,
                             __nv_bfloat16* __restrict__ h,
                             __nv_bfloat16* __restrict__ l, int n4) {
    int i = blockIdx.x * blockDim.x + threadIdx.x;
    if (i >= n4) return;
    float4 v = reinterpret_cast<const float4*>(s)[i];
    __nv_bfloat16 h0,l0,h1,l1,h2,l2,h3,l3;
    splitf(v.x, h0, l0); splitf(v.y, h1, l1);
    splitf(v.z, h2, l2); splitf(v.w, h3, l3);
    __nv_bfloat162 ph0; ph0.x=h0; ph0.y=h1;
    __nv_bfloat162 ph1; ph1.x=h2; ph1.y=h3;
    __nv_bfloat162 pl0; pl0.x=l0; pl0.y=l1;
    __nv_bfloat162 pl1; pl1.x=l2; pl1.y=l3;
    reinterpret_cast<__nv_bfloat162*>(h)[2*i]   = ph0;
    reinterpret_cast<__nv_bfloat162*>(h)[2*i+1] = ph1;
    reinterpret_cast<__nv_bfloat162*>(l)[2*i]   = pl0;
    reinterpret_cast<__nv_bfloat162*>(l)[2*i+1] = pl1;
}

// ---------------- embed ----------------
__global__ void embed_kernel(const int* __restrict__ tok,
                             const float* __restrict__ emb,
                             const float* __restrict__ pos,
                             float* __restrict__ x) {
    int idx = blockIdx.x * blockDim.x + threadIdx.x;
    if (idx >= MR*Dm) return;
    int row = idx / Dm, d = idx % Dm;
    int s = row % Sm;
    int t = tok[row];
    x[idx] = emb[t*Dm + d] + pos[s*Dm + d];
}

// ---------------- layernorm -> bf16 hi/lo ----------------
__global__ void __launch_bounds__(128) ln_kernel(const float* __restrict__ x,
                                                 const float* __restrict__ g,
                                                 const float* __restrict__ b,
                                                 __nv_bfloat16* __restrict__ oh,
                                                 __nv_bfloat16* __restrict__ ol) {
    int row = blockIdx.x;
    int t = threadIdx.x;
    const float4 v4 = reinterpret_cast<const float4*>(x + (size_t)row*Dm)[t];
    __shared__ float red[4];

    float s = v4.x + v4.y + v4.z + v4.w;
    #pragma unroll
    for (int o = 16; o > 0; o >>= 1) s += __shfl_xor_sync(0xffffffffu, s, o);
    if ((t & 31) == 0) red[t >> 5] = s;
    __syncthreads();
    float mean = (red[0] + red[1] + red[2] + red[3]) * (1.0f/Dm);
    __syncthreads();

    float dx = v4.x-mean, dy = v4.y-mean, dz = v4.z-mean, dw = v4.w-mean;
    float ss = dx*dx + dy*dy + dz*dz + dw*dw;
    #pragma unroll
    for (int o = 16; o > 0; o >>= 1) ss += __shfl_xor_sync(0xffffffffu, ss, o);
    if ((t & 31) == 0) red[t >> 5] = ss;
    __syncthreads();
    float var = (red[0] + red[1] + red[2] + red[3]) * (1.0f/Dm);
    float inv = rsqrtf(var + 1e-5f);

    float4 gg = reinterpret_cast<const float4*>(g)[t];
    float4 bb = reinterpret_cast<const float4*>(b)[t];
    float o0 = dx*inv*gg.x + bb.x;
    float o1 = dy*inv*gg.y + bb.y;
    float o2 = dz*inv*gg.z + bb.z;
    float o3 = dw*inv*gg.w + bb.w;

    __nv_bfloat16 h0,l0,h1,l1,h2,l2,h3,l3;
    splitf(o0,h0,l0); splitf(o1,h1,l1); splitf(o2,h2,l2); splitf(o3,h3,l3);
    size_t off = (size_t)row*Dm + 4*t;
    __nv_bfloat162 p;
    p.x=h0; p.y=h1; *reinterpret_cast<__nv_bfloat162*>(oh+off)   = p;
    p.x=h2; p.y=h3; *reinterpret_cast<__nv_bfloat162*>(oh+off+2) = p;
    p.x=l0; p.y=l1; *reinterpret_cast<__nv_bfloat162*>(ol+off)   = p;
    p.x=l2; p.y=l3; *reinterpret_cast<__nv_bfloat162*>(ol+off+2) = p;
}

// ---------------- split-bf16 tensor-core GEMM ----------------
// C[M,N] = act(A[M,K] @ W[N,K]^T + bias) (+Rsd / or split-bf16 out)
// A = Ah + Al, W = Wh + Wl; acc += Ah*Wh + Ah*Wl + Al*Wh  (err ~2^-18)
// Tiles: BM=128, BN=128, BK=32; 512 threads = 16 warps (4x4), warp tile 32x32.
// ACT: 0 none, 1 exact-erf GELU. OUTMODE: 0 fp32 C; 1 fp32 C + residual; 2 bf16 hi/lo out.
#define BMg 128
#define BNg 128
#define BKg 32
template<int ACT, int OUTMODE>
__global__ void __launch_bounds__(512)
bgemm(const __nv_bfloat16* __restrict__ Ah, const __nv_bfloat16* __restrict__ Al,
      const __nv_bfloat16* __restrict__ Wh, const __nv_bfloat16* __restrict__ Wl,
      const float* __restrict__ bias, const float* __restrict__ Rsd,
      float* __restrict__ C, __nv_bfloat16* __restrict__ Ch, __nv_bfloat16* __restrict__ Cl,
      int Mn, int Nn, int Kn) {
    __shared__ __nv_bfloat16 Ahs[BMg][BKg+8];
    __shared__ __nv_bfloat16 Als[BMg][BKg+8];
    __shared__ __nv_bfloat16 Whs[BNg][BKg+8];
    __shared__ __nv_bfloat16 Wls[BNg][BKg+8];

    int tid  = threadIdx.x;
    int lane = tid & 31, warp = tid >> 5;
    int m0 = (warp >> 2) * 32;     // warp m offset within tile
    int n0 = (warp & 3) * 32;      // warp n offset within tile
    int bm = blockIdx.y * BMg;
    int bn = blockIdx.x * BNg;

    float acc[2][4][4];
    #pragma unroll
    for (int i = 0; i < 2; i++)
        #pragma unroll
        for (int j = 0; j < 4; j++)
            #pragma unroll
            for (int r = 0; r < 4; r++) acc[i][j][r] = 0.f;

    for (int k0 = 0; k0 < Kn; k0 += BKg) {
        // load A tiles (hi/lo), 8 halves per uint2-pair -> 4-half uint2 units
        #pragma unroll
        for (int i = tid; i < BMg*BKg/4; i += 512) {
            int m = i >> 3, kq = (i & 7) << 2;
            size_t go = (size_t)(bm + m)*Kn + k0 + kq;
            *reinterpret_cast<uint2*>(&Ahs[m][kq]) = *reinterpret_cast<const uint2*>(Ah + go);
            *reinterpret_cast<uint2*>(&Als[m][kq]) = *reinterpret_cast<const uint2*>(Al + go);
        }
        // load W tiles (hi/lo) with ragged-N guard
        #pragma unroll
        for (int i = tid; i < BNg*BKg/4; i += 512) {
            int n = i >> 3, kq = (i & 7) << 2;
            int gn = bn + n;
            uint2 vh = make_uint2(0u,0u), vl = make_uint2(0u,0u);
            if (gn < Nn) {
                size_t go = (size_t)gn*Kn + k0 + kq;
                vh = *reinterpret_cast<const uint2*>(Wh + go);
                vl = *reinterpret_cast<const uint2*>(Wl + go);
            }
            *reinterpret_cast<uint2*>(&Whs[n][kq]) = vh;
            *reinterpret_cast<uint2*>(&Wls[n][kq]) = vl;
        }
        __syncthreads();

        #pragma unroll
        for (int ks = 0; ks < BKg; ks += 16) {
            unsigned afh[2][4], afl[2][4], bfh[4][2], bfl[4][2];
            #pragma unroll
            for (int i = 0; i < 2; i++) {
                int r = m0 + i*16 + (lane & 15);
                int c = ks + (lane >> 4) * 8;
                ldsm4(afh[i], saddr(&Ahs[r][c]));
                ldsm4(afl[i], saddr(&Als[r][c]));
            }
            #pragma unroll
            for (int j = 0; j < 4; j++) {
                int r = n0 + j*8 + (lane & 7);
                int c = ks + ((lane >> 3) & 1) * 8;
                ldsm2(bfh[j], saddr(&Whs[r][c]));
                ldsm2(bfl[j], saddr(&Wls[r][c]));
            }
            #pragma unroll
            for (int i = 0; i < 2; i++)
                #pragma unroll
                for (int j = 0; j < 4; j++) {
                    mma16816(acc[i][j], afh[i], bfh[j]);
                    mma16816(acc[i][j], afh[i], bfl[j]);
                    mma16816(acc[i][j], afl[i], bfh[j]);
                }
        }
        __syncthreads();
    }

    // epilogue
    #pragma unroll
    for (int i = 0; i < 2; i++) {
        #pragma unroll
        for (int j = 0; j < 4; j++) {
            int r0 = bm + m0 + i*16 + (lane >> 2);
            int cc = bn + n0 + j*8 + ((lane & 3) << 1);
            #pragma unroll
            for (int hr = 0; hr < 2; hr++) {
                int r = r0 + hr*8;
                float v0 = acc[i][j][hr*2+0];
                float v1 = acc[i][j][hr*2+1];
                if (OUTMODE == 2) {
                    v0 += bias[cc]; v1 += bias[cc+1];
                    if (ACT) {
                        v0 = 0.5f * v0 * (1.0f + erff(v0 * 0.70710678118654752f));
                        v1 = 0.5f * v1 * (1.0f + erff(v1 * 0.70710678118654752f));
                    }
                    __nv_bfloat16 h0,l0,h1,l1;
                    splitf(v0,h0,l0); splitf(v1,h1,l1);
                    __nv_bfloat162 ph; ph.x=h0; ph.y=h1;
                    __nv_bfloat162 pl; pl.x=l0; pl.y=l1;
                    *reinterpret_cast<__nv_bfloat162*>(Ch + (size_t)r*Nn + cc) = ph;
                    *reinterpret_cast<__nv_bfloat162*>(Cl + (size_t)r*Nn + cc) = pl;
                } else {
                    if (cc < Nn) {
                        float v = v0 + bias[cc];
                        if (ACT) v = 0.5f * v * (1.0f + erff(v * 0.70710678118654752f));
                        if (OUTMODE == 1) v += Rsd[(size_t)r*Nn + cc];
                        C[(size_t)r*Nn + cc] = v;
                    }
                    if (cc + 1 < Nn) {
                        float v = v1 + bias[cc+1];
                        if (ACT) v = 0.5f * v * (1.0f + erff(v * 0.70710678118654752f));
                        if (OUTMODE == 1) v += Rsd[(size_t)r*Nn + cc + 1];
                        C[(size_t)r*Nn + cc + 1] = v;
                    }
                }
            }
        }
    }
}

// ---------------- attention: flash-style fp32, online softmax, bf16 hi/lo out ----------------
__global__ void __launch_bounds__(64)
attn_kernel(const float* __restrict__ q, const float* __restrict__ k,
            const float* __restrict__ v,
            __nv_bfloat16* __restrict__ oh, __nv_bfloat16* __restrict__ ol) {
    int qt = blockIdx.x;
    int bh = blockIdx.y;
    int b = bh / Hh, h = bh % Hh;
    int t = threadIdx.x;
    int qi = qt*64 + t;
    int rowbase = b * Sm;

    __shared__ float Ks[64][DK];
    __shared__ float Vs[64][DK];

    float qr[DK];
    {
        const float4* qp = reinterpret_cast<const float4*>(q + (size_t)(rowbase+qi)*Dm + h*DK);
        #pragma unroll
        for (int d4 = 0; d4 < DK/4; d4++) {
            float4 x = qp[d4];
            qr[4*d4]=x.x; qr[4*d4+1]=x.y; qr[4*d4+2]=x.z; qr[4*d4+3]=x.w;
        }
    }

    float m = -1e30f, l = 0.f;
    float acc[DK];
    #pragma unroll
    for (int d = 0; d < DK; d++) acc[d] = 0.f;

    for (int kt = 0; kt <= qt; kt++) {
        __syncthreads();
        #pragma unroll
        for (int it = 0; it < 16; it++) {
            int r = it*4 + (t >> 4);
            int c = (t & 15) * 4;
            size_t off = (size_t)(rowbase + kt*64 + r)*Dm + h*DK + c;
            *reinterpret_cast<float4*>(&Ks[r][c]) = *reinterpret_cast<const float4*>(k + off);
            *reinterpret_cast<float4*>(&Vs[r][c]) = *reinterpret_cast<const float4*>(v + off);
        }
        __syncthreads();

        int jmax = (kt == qt) ? t : 63;
        for (int j = 0; j <= jmax; j++) {
            float s0=0.f, s1=0.f, s2=0.f, s3=0.f;
            const float4* kv = reinterpret_cast<const float4*>(Ks[j]);
            #pragma unroll
            for (int d4 = 0; d4 < DK/4; d4++) {
                float4 kk4 = kv[d4];
                s0 += qr[4*d4  ]*kk4.x;
                s1 += qr[4*d4+1]*kk4.y;
                s2 += qr[4*d4+2]*kk4.z;
                s3 += qr[4*d4+3]*kk4.w;
            }
            float s = ((s0+s1)+(s2+s3)) * 0.125f;

            if (s > m) {
                float corr = __expf(m - s);
                l *= corr;
                #pragma unroll
                for (int d = 0; d < DK; d++) acc[d] *= corr;
                m = s;
            }
            float p = __expf(s - m);
            l += p;
            const float4* vv = reinterpret_cast<const float4*>(Vs[j]);
            #pragma unroll
            for (int d4 = 0; d4 < DK/4; d4++) {
                float4 v4 = vv[d4];
                acc[4*d4  ] += p*v4.x;
                acc[4*d4+1] += p*v4.y;
                acc[4*d4+2] += p*v4.z;
                acc[4*d4+3] += p*v4.w;
            }
        }
    }

    float inv = 1.f / l;
    size_t off = (size_t)(rowbase+qi)*Dm + h*DK;
    #pragma unroll
    for (int d4 = 0; d4 < DK/4; d4++) {
        float v0 = acc[4*d4  ]*inv;
        float v1 = acc[4*d4+1]*inv;
        float v2 = acc[4*d4+2]*inv;
        float v3 = acc[4*d4+3]*inv;
        __nv_bfloat16 h0,l0,h1,l1,h2,l2,h3,l3;
        splitf(v0,h0,l0); splitf(v1,h1,l1); splitf(v2,h2,l2); splitf(v3,h3,l3);
        __nv_bfloat162 p;
        p.x=h0; p.y=h1; *reinterpret_cast<__nv_bfloat162*>(oh+off+4*d4)   = p;
        p.x=h2; p.y=h3; *reinterpret_cast<__nv_bfloat162*>(oh+off+4*d4+2) = p;
        p.x=l0; p.y=l1; *reinterpret_cast<__nv_bfloat162*>(ol+off+4*d4)   = p;
        p.x=l2; p.y=l3; *reinterpret_cast<__nv_bfloat162*>(ol+off+4*d4+2) = p;
    }
}

// ---------------- launch ----------------
extern "C" void kernel_launch(void* const* d_in, const int* in_sizes, int n_in,
                              void* d_out, int out_size) {
    const int*   tokens = (const int*)  d_in[0];
    const float* emb    = (const float*)d_in[1];
    const float* pos    = (const float*)d_in[2];
    const float* Wq     = (const float*)d_in[3];
    const float* bq     = (const float*)d_in[4];
    const float* Wk     = (const float*)d_in[5];
    const float* bk     = (const float*)d_in[6];
    const float* Wv     = (const float*)d_in[7];
    const float* bv     = (const float*)d_in[8];
    const float* Wo     = (const float*)d_in[9];
    const float* bo     = (const float*)d_in[10];
    const float* ln1g   = (const float*)d_in[11];
    const float* ln1b   = (const float*)d_in[12];
    const float* W1     = (const float*)d_in[13];
    const float* b1     = (const float*)d_in[14];
    const float* W2     = (const float*)d_in[15];
    const float* b2     = (const float*)d_in[16];
    const float* ln2g   = (const float*)d_in[17];
    const float* ln2b   = (const float*)d_in[18];
    const float* lnfg   = (const float*)d_in[19];
    const float* lnfb   = (const float*)d_in[20];
    const float* Whead  = (const float*)d_in[21];
    const float* bhead  = (const float*)d_in[22];
    float* out = (float*)d_out;

    float *x, *q, *k, *v;
    __nv_bfloat16 *hh,*hl,*oh,*ol,*fh,*fl;
    __nv_bfloat16 *wqh,*wql,*wkh,*wkl,*wvh,*wvl,*woh,*wol,*w1h,*w1l,*w2h,*w2l,*whh,*whl;
    cudaGetSymbolAddress((void**)&x, g_x);
    cudaGetSymbolAddress((void**)&q, g_q);
    cudaGetSymbolAddress((void**)&k, g_k);
    cudaGetSymbolAddress((void**)&v, g_v);
    cudaGetSymbolAddress((void**)&hh, g_hh); cudaGetSymbolAddress((void**)&hl, g_hl);
    cudaGetSymbolAddress((void**)&oh, g_oh); cudaGetSymbolAddress((void**)&ol, g_ol);
    cudaGetSymbolAddress((void**)&fh, g_fh); cudaGetSymbolAddress((void**)&fl, g_fl);
    cudaGetSymbolAddress((void**)&wqh, g_wqh); cudaGetSymbolAddress((void**)&wql, g_wql);
    cudaGetSymbolAddress((void**)&wkh, g_wkh); cudaGetSymbolAddress((void**)&wkl, g_wkl);
    cudaGetSymbolAddress((void**)&wvh, g_wvh); cudaGetSymbolAddress((void**)&wvl, g_wvl);
    cudaGetSymbolAddress((void**)&woh, g_woh); cudaGetSymbolAddress((void**)&wol, g_wol);
    cudaGetSymbolAddress((void**)&w1h, g_w1h); cudaGetSymbolAddress((void**)&w1l, g_w1l);
    cudaGetSymbolAddress((void**)&w2h, g_w2h); cudaGetSymbolAddress((void**)&w2l, g_w2l);
    cudaGetSymbolAddress((void**)&whh, g_whh); cudaGetSymbolAddress((void**)&whl, g_whl);

    // split all weights to bf16 hi/lo (cheap, bandwidth-bound)
    const int TS = 256;
    int nA = Lm*Dm*Dm/4, nF = Lm*DFFm*Dm/4, nH = (int)((size_t)Vv*Dm/4);
    split_kernel<<<(nA+TS-1)/TS, TS>>>(Wq, wqh, wql, nA);
    split_kernel<<<(nA+TS-1)/TS, TS>>>(Wk, wkh, wkl, nA);
    split_kernel<<<(nA+TS-1)/TS, TS>>>(Wv, wvh, wvl, nA);
    split_kernel<<<(nA+TS-1)/TS, TS>>>(Wo, woh, wol, nA);
    split_kernel<<<(nF+TS-1)/TS, TS>>>(W1, w1h, w1l, nF);
    split_kernel<<<(nF+TS-1)/TS, TS>>>(W2, w2h, w2l, nF);
    split_kernel<<<(nH+TS-1)/TS, TS>>>(Whead, whh, whl, nH);

    embed_kernel<<<(MR*Dm + 255)/256, 256>>>(tokens, emb, pos, x);

    dim3 gQKV(Dm/BNg,  MR/BMg);                 // (4,16)
    dim3 gFF1(DFFm/BNg, MR/BMg);                // (16,16)
    dim3 gHead((Vv + BNg - 1)/BNg, MR/BMg);     // (393,16)
    dim3 gAttn(Sm/64, Bb*Hh);

    for (int l = 0; l < Lm; l++) {
        size_t oA = (size_t)l*Dm*Dm, oF1 = (size_t)l*DFFm*Dm, oF2 = (size_t)l*Dm*DFFm;

        ln_kernel<<<MR, 128>>>(x, ln1g + l*Dm, ln1b + l*Dm, hh, hl);
        bgemm<0,0><<<gQKV,512>>>(hh, hl, wqh+oA, wql+oA, bq+l*Dm, nullptr, q, nullptr, nullptr, MR, Dm, Dm);
        bgemm<0,0><<<gQKV,512>>>(hh, hl, wkh+oA, wkl+oA, bk+l*Dm, nullptr, k, nullptr, nullptr, MR, Dm, Dm);
        bgemm<0,0><<<gQKV,512>>>(hh, hl, wvh+oA, wvl+oA, bv+l*Dm, nullptr, v, nullptr, nullptr, MR, Dm, Dm);
        attn_kernel<<<gAttn, 64>>>(q, k, v, oh, ol);
        bgemm<0,1><<<gQKV,512>>>(oh, ol, woh+oA, wol+oA, bo+l*Dm, x, x, nullptr, nullptr, MR, Dm, Dm);

        ln_kernel<<<MR, 128>>>(x, ln2g + l*Dm, ln2b + l*Dm, hh, hl);
        bgemm<1,2><<<gFF1,512>>>(hh, hl, w1h+oF1, w1l+oF1, b1+l*DFFm, nullptr, nullptr, fh, fl, MR, DFFm, Dm);
        bgemm<0,1><<<gQKV,512>>>(fh, fl, w2h+oF2, w2l+oF2, b2+l*Dm, x, x, nullptr, nullptr, MR, Dm, DFFm);
    }

    ln_kernel<<<MR, 128>>>(x, lnfg, lnfb, hh, hl);
    bgemm<0,0><<<gHead,512>>>(hh, hl, whh, whl, bhead, nullptr, out, nullptr, nullptr, MR, Vv, Dm);
}

// round 5
// speedup vs baseline: 1.7248x; 1.2502x over previous
#include <cuda_runtime.h>
#include <cuda_bf16.h>
#include <math.h>
#include <stdint.h>

#define Dm   512
#define Hh   8
#define DK   64
#define DFFm 2048
#define Lm   4
#define Bb   2
#define Sm   1024
#define Vv   50257
#define MR   (Bb*Sm)   // 2048 rows
#define NQKV (3*Dm)    // 1536

// ---------------- scratch (device globals; no allocs allowed) ----------------
__device__ float g_x[MR*Dm];
__device__ float g_qkv[MR*NQKV];

__device__ __nv_bfloat16 g_hh[MR*Dm],  g_hl[MR*Dm];     // LN output hi/lo
__device__ __nv_bfloat16 g_oh[MR*Dm],  g_ol[MR*Dm];     // attn output hi/lo
__device__ __nv_bfloat16 g_fh[MR*DFFm], g_fl[MR*DFFm];  // FFN1/GELU output hi/lo

__device__ __nv_bfloat16 g_wqkvh[Lm*NQKV*Dm], g_wqkvl[Lm*NQKV*Dm];
__device__ float         g_bqkv[Lm*NQKV];
__device__ __nv_bfloat16 g_woh[Lm*Dm*Dm],   g_wol[Lm*Dm*Dm];
__device__ __nv_bfloat16 g_w1h[Lm*DFFm*Dm], g_w1l[Lm*DFFm*Dm];
__device__ __nv_bfloat16 g_w2h[Lm*Dm*DFFm], g_w2l[Lm*Dm*DFFm];
__device__ __nv_bfloat16 g_whh[(size_t)Vv*Dm], g_whl[(size_t)Vv*Dm];

// ---------------- small helpers ----------------
__device__ __forceinline__ void splitf(float v, __nv_bfloat16& h, __nv_bfloat16& l) {
    h = __float2bfloat16(v);
    l = __float2bfloat16(v - __bfloat162float(h));
}
__device__ __forceinline__ unsigned saddr(const void* p) {
    return (unsigned)__cvta_generic_to_shared(p);
}
__device__ __forceinline__ void ldsm4(unsigned* d, unsigned a) {
    asm volatile("ldmatrix.sync.aligned.m8n8.x4.shared.b16 {%0,%1,%2,%3}, [%4];"
        : "=r"(d[0]), "=r"(d[1]), "=r"(d[2]), "=r"(d[3]) : "r"(a));
}
__device__ __forceinline__ void mma16816(float* c, const unsigned* a, const unsigned* b) {
    asm volatile("mma.sync.aligned.m16n8k16.row.col.f32.bf16.bf16.f32 "
        "{%0,%1,%2,%3}, {%4,%5,%6,%7}, {%8,%9}, {%0,%1,%2,%3};"
        : "+f"(c[0]), "+f"(c[1]), "+f"(c[2]), "+f"(c[3])
        : "r"(a[0]), "r"(a[1]), "r"(a[2]), "r"(a[3]), "r"(b[0]), "r"(b[1]));
}
__device__ __forceinline__ void cp16(uint32_t d, const void* s) {
    asm volatile("cp.async.cg.shared.global [%0], [%1], 16;" :: "r"(d), "l"(s));
}
__device__ __forceinline__ void cp16z(uint32_t d, const void* s, bool ok) {
    int sz = ok ? 16 : 0;
    asm volatile("cp.async.cg.shared.global [%0], [%1], 16, %2;" :: "r"(d), "l"(s), "r"(sz));
}
__device__ __forceinline__ float gelu(float v) {
    return 0.5f * v * (1.0f + erff(v * 0.70710678118654752f));
}

// ---------------- weight split: fp32 -> bf16 hi/lo ----------------
__global__ void split_kernel(const float* __restrict__ s,
                             __nv_bfloat16* __restrict__ h,
                             __nv_bfloat16* __restrict__ l, int n4) {
    int i = blockIdx.x * blockDim.x + threadIdx.x;
    if (i >= n4) return;
    float4 v = reinterpret_cast<const float4*>(s)[i];
    __nv_bfloat16 h0,l0,h1,l1,h2,l2,h3,l3;
    splitf(v.x, h0, l0); splitf(v.y, h1, l1);
    splitf(v.z, h2, l2); splitf(v.w, h3, l3);
    __nv_bfloat162 ph0; ph0.x=h0; ph0.y=h1;
    __nv_bfloat162 ph1; ph1.x=h2; ph1.y=h3;
    __nv_bfloat162 pl0; pl0.x=l0; pl0.y=l1;
    __nv_bfloat162 pl1; pl1.x=l2; pl1.y=l3;
    reinterpret_cast<__nv_bfloat162*>(h)[2*i]   = ph0;
    reinterpret_cast<__nv_bfloat162*>(h)[2*i+1] = ph1;
    reinterpret_cast<__nv_bfloat162*>(l)[2*i]   = pl0;
    reinterpret_cast<__nv_bfloat162*>(l)[2*i+1] = pl1;
}

__global__ void pack_bias_kernel(const float* __restrict__ bq, const float* __restrict__ bk,
                                 const float* __restrict__ bv, float* __restrict__ o) {
    int i = blockIdx.x * blockDim.x + threadIdx.x;
    if (i >= Lm*NQKV) return;
    int l = i / NQKV, c = i % NQKV;
    float v = (c < Dm) ? bq[l*Dm + c] : (c < 2*Dm ? bk[l*Dm + c - Dm] : bv[l*Dm + c - 2*Dm]);
    o[i] = v;
}

// ---------------- embed ----------------
__global__ void embed_kernel(const int* __restrict__ tok,
                             const float* __restrict__ emb,
                             const float* __restrict__ pos,
                             float* __restrict__ x) {
    int idx = blockIdx.x * blockDim.x + threadIdx.x;
    if (idx >= MR*Dm) return;
    int row = idx / Dm, d = idx % Dm;
    int s = row % Sm;
    int t = tok[row];
    x[idx] = emb[t*Dm + d] + pos[s*Dm + d];
}

// ---------------- layernorm -> bf16 hi/lo ----------------
__global__ void __launch_bounds__(128) ln_kernel(const float* __restrict__ x,
                                                 const float* __restrict__ g,
                                                 const float* __restrict__ b,
                                                 __nv_bfloat16* __restrict__ oh,
                                                 __nv_bfloat16* __restrict__ ol) {
    int row = blockIdx.x;
    int t = threadIdx.x;
    const float4 v4 = reinterpret_cast<const float4*>(x + (size_t)row*Dm)[t];
    __shared__ float red[4];

    float s = v4.x + v4.y + v4.z + v4.w;
    #pragma unroll
    for (int o = 16; o > 0; o >>= 1) s += __shfl_xor_sync(0xffffffffu, s, o);
    if ((t & 31) == 0) red[t >> 5] = s;
    __syncthreads();
    float mean = (red[0] + red[1] + red[2] + red[3]) * (1.0f/Dm);
    __syncthreads();

    float dx = v4.x-mean, dy = v4.y-mean, dz = v4.z-mean, dw = v4.w-mean;
    float ss = dx*dx + dy*dy + dz*dz + dw*dw;
    #pragma unroll
    for (int o = 16; o > 0; o >>= 1) ss += __shfl_xor_sync(0xffffffffu, ss, o);
    if ((t & 31) == 0) red[t >> 5] = ss;
    __syncthreads();
    float var = (red[0] + red[1] + red[2] + red[3]) * (1.0f/Dm);
    float inv = rsqrtf(var + 1e-5f);

    float4 gg = reinterpret_cast<const float4*>(g)[t];
    float4 bb = reinterpret_cast<const float4*>(b)[t];
    float o0 = dx*inv*gg.x + bb.x;
    float o1 = dy*inv*gg.y + bb.y;
    float o2 = dz*inv*gg.z + bb.z;
    float o3 = dw*inv*gg.w + bb.w;

    __nv_bfloat16 h0,l0,h1,l1,h2,l2,h3,l3;
    splitf(o0,h0,l0); splitf(o1,h1,l1); splitf(o2,h2,l2); splitf(o3,h3,l3);
    size_t off = (size_t)row*Dm + 4*t;
    __nv_bfloat162 p;
    p.x=h0; p.y=h1; *reinterpret_cast<__nv_bfloat162*>(oh+off)   = p;
    p.x=h2; p.y=h3; *reinterpret_cast<__nv_bfloat162*>(oh+off+2) = p;
    p.x=l0; p.y=l1; *reinterpret_cast<__nv_bfloat162*>(ol+off)   = p;
    p.x=l2; p.y=l3; *reinterpret_cast<__nv_bfloat162*>(ol+off+2) = p;
}

// ---------------- pipelined split-bf16 HMMA GEMM ----------------
// C[M,N] = act(A[M,K] @ W[N,K]^T + bias) ; A=Ah+Al, W=Wh+Wl, 3 MMAs (hh,hl,lh)
// BM=128, BK=32, BN in {64,128}; THREADS=BN*4; 3-stage cp.async pipeline.
// ACT: 0 none, 1 GELU. OUTMODE: 0 fp32 C; 1 fp32 + residual; 2 bf16 hi/lo out.
template<int BN, int ACT, int OUTMODE>
__global__ void __launch_bounds__(BN*4)
pgemm(const __nv_bfloat16* __restrict__ Ah, const __nv_bfloat16* __restrict__ Al,
      const __nv_bfloat16* __restrict__ Wh, const __nv_bfloat16* __restrict__ Wl,
      const float* __restrict__ bias, const float* __restrict__ Rsd,
      float* __restrict__ C, __nv_bfloat16* __restrict__ Ch, __nv_bfloat16* __restrict__ Cl,
      int Nn, int Kn) {
    constexpr int BM = 128, BK = 32;
    constexpr int THREADS = BN*4;
    constexpr int AST = BM*40;                 // halves per A tile (padded stride 40)
    constexpr int WST = BN*40;
    constexpr int OFF_AL = AST*2;              // byte offsets inside a stage
    constexpr int OFF_WH = 2*AST*2;
    constexpr int OFF_WL = (2*AST + WST)*2;
    constexpr int STAGE_B = (2*AST + 2*WST)*2;

    extern __shared__ __align__(16) char smem[];
    uint32_t sb = saddr(smem);

    int tid  = threadIdx.x;
    int lane = tid & 31, warp = tid >> 5;
    int m0 = (warp & 3) * 32;
    int n0 = (warp >> 2) * 32;
    int bm = blockIdx.y * BM;
    int bn = blockIdx.x * BN;
    int nK = Kn / BK;

    float acc[2][4][4];
    #pragma unroll
    for (int i = 0; i < 2; i++)
        #pragma unroll
        for (int j = 0; j < 4; j++)
            #pragma unroll
            for (int r = 0; r < 4; r++) acc[i][j][r] = 0.f;

    auto load_stage = [&](int s, int kt) {
        uint32_t base = sb + s*STAGE_B;
        int k0 = kt*BK;
        #pragma unroll
        for (int i = tid; i < BM*4; i += THREADS) {
            int r = i >> 2, c = (i & 3) << 3;
            uint32_t d = base + (r*40 + c)*2;
            size_t g = (size_t)(bm + r)*Kn + k0 + c;
            cp16(d,          Ah + g);
            cp16(d + OFF_AL, Al + g);
        }
        #pragma unroll
        for (int i = tid; i < BN*4; i += THREADS) {
            int r = i >> 2, c = (i & 3) << 3;
            int gn = bn + r;
            uint32_t d = base + OFF_WH + (r*40 + c)*2;
            size_t g = (size_t)gn*Kn + k0 + c;
            bool ok = gn < Nn;
            cp16z(d,                     Wh + g, ok);
            cp16z(d + (OFF_WL - OFF_WH), Wl + g, ok);
        }
        asm volatile("cp.async.commit_group;" ::: "memory");
    };

    load_stage(0, 0);
    load_stage(1, 1);

    for (int kt = 0; kt < nK; kt++) {
        if (kt == nK - 1) asm volatile("cp.async.wait_group 0;" ::: "memory");
        else              asm volatile("cp.async.wait_group 1;" ::: "memory");
        __syncthreads();
        if (kt + 2 < nK) load_stage((kt + 2) % 3, kt + 2);

        uint32_t base = sb + (kt % 3)*STAGE_B;
        #pragma unroll
        for (int ks = 0; ks < 2; ks++) {
            unsigned ah[2][4], al[2][4], bh[2][4], bl[2][4];
            int ca = ks*16 + ((lane >> 4) << 3);
            #pragma unroll
            for (int i = 0; i < 2; i++) {
                int rw = m0 + i*16 + (lane & 15);
                uint32_t ad = base + (rw*40 + ca)*2;
                ldsm4(ah[i], ad);
                ldsm4(al[i], ad + OFF_AL);
            }
            int cb = ks*16 + (((lane >> 3) & 1) << 3);
            #pragma unroll
            for (int j = 0; j < 2; j++) {
                int rw = n0 + j*16 + ((lane >> 4) << 3) + (lane & 7);
                uint32_t bd = base + OFF_WH + (rw*40 + cb)*2;
                ldsm4(bh[j], bd);
                ldsm4(bl[j], bd + (OFF_WL - OFF_WH));
            }
            #pragma unroll
            for (int i = 0; i < 2; i++)
                #pragma unroll
                for (int jj = 0; jj < 4; jj++) {
                    const unsigned* bfh = &bh[jj >> 1][(jj & 1)*2];
                    const unsigned* bfl = &bl[jj >> 1][(jj & 1)*2];
                    mma16816(acc[i][jj], ah[i], bfh);
                    mma16816(acc[i][jj], ah[i], bfl);
                    mma16816(acc[i][jj], al[i], bfh);
                }
        }
    }

    // epilogue
    bool vecok = ((Nn & 1) == 0) && (bn + BN <= Nn);
    #pragma unroll
    for (int i = 0; i < 2; i++) {
        #pragma unroll
        for (int jj = 0; jj < 4; jj++) {
            int r0 = bm + m0 + i*16 + (lane >> 2);
            int cc = bn + n0 + (jj >> 1)*16 + (jj & 1)*8 + ((lane & 3) << 1);
            #pragma unroll
            for (int hr = 0; hr < 2; hr++) {
                int r = r0 + hr*8;
                float v0 = acc[i][jj][hr*2 + 0];
                float v1 = acc[i][jj][hr*2 + 1];
                if (OUTMODE == 2) {
                    v0 += bias[cc]; v1 += bias[cc+1];
                    if (ACT) { v0 = gelu(v0); v1 = gelu(v1); }
                    __nv_bfloat16 h0,l0,h1,l1;
                    splitf(v0,h0,l0); splitf(v1,h1,l1);
                    __nv_bfloat162 ph; ph.x=h0; ph.y=h1;
                    __nv_bfloat162 pl; pl.x=l0; pl.y=l1;
                    *reinterpret_cast<__nv_bfloat162*>(Ch + (size_t)r*Nn + cc) = ph;
                    *reinterpret_cast<__nv_bfloat162*>(Cl + (size_t)r*Nn + cc) = pl;
                } else if (vecok) {
                    float2 v;
                    v.x = v0 + bias[cc];
                    v.y = v1 + bias[cc+1];
                    if (ACT) { v.x = gelu(v.x); v.y = gelu(v.y); }
                    if (OUTMODE == 1) {
                        float2 r2 = *reinterpret_cast<const float2*>(Rsd + (size_t)r*Nn + cc);
                        v.x += r2.x; v.y += r2.y;
                    }
                    *reinterpret_cast<float2*>(C + (size_t)r*Nn + cc) = v;
                } else {
                    if (cc < Nn) {
                        float v = v0 + bias[cc];
                        if (ACT) v = gelu(v);
                        if (OUTMODE == 1) v += Rsd[(size_t)r*Nn + cc];
                        C[(size_t)r*Nn + cc] = v;
                    }
                    if (cc + 1 < Nn) {
                        float v = v1 + bias[cc+1];
                        if (ACT) v = gelu(v);
                        if (OUTMODE == 1) v += Rsd[(size_t)r*Nn + cc + 1];
                        C[(size_t)r*Nn + cc + 1] = v;
                    }
                }
            }
        }
    }
}

// ---------------- attention: flash-style fp32 over fused qkv buffer ----------------
// qkv layout: [MR][1536]: q at col h*64, k at 512+h*64, v at 1024+h*64
__global__ void __launch_bounds__(64)
attn_kernel(const float* __restrict__ qkv,
            __nv_bfloat16* __restrict__ oh, __nv_bfloat16* __restrict__ ol) {
    int qt = blockIdx.x;
    int bh = blockIdx.y;
    int b = bh / Hh, h = bh % Hh;
    int t = threadIdx.x;
    int qi = qt*64 + t;
    int rowbase = b * Sm;

    __shared__ float Ks[64][DK];
    __shared__ float Vs[64][DK];

    float qr[DK];
    {
        const float4* qp = reinterpret_cast<const float4*>(qkv + (size_t)(rowbase+qi)*NQKV + h*DK);
        #pragma unroll
        for (int d4 = 0; d4 < DK/4; d4++) {
            float4 x = qp[d4];
            qr[4*d4]=x.x; qr[4*d4+1]=x.y; qr[4*d4+2]=x.z; qr[4*d4+3]=x.w;
        }
    }

    float m = -1e30f, l = 0.f;
    float acc[DK];
    #pragma unroll
    for (int d = 0; d < DK; d++) acc[d] = 0.f;

    for (int kt = 0; kt <= qt; kt++) {
        __syncthreads();
        #pragma unroll
        for (int it = 0; it < 16; it++) {
            int r = it*4 + (t >> 4);
            int c = (t & 15) * 4;
            size_t base = (size_t)(rowbase + kt*64 + r)*NQKV + h*DK + c;
            *reinterpret_cast<float4*>(&Ks[r][c]) = *reinterpret_cast<const float4*>(qkv + base + Dm);
            *reinterpret_cast<float4*>(&Vs[r][c]) = *reinterpret_cast<const float4*>(qkv + base + 2*Dm);
        }
        __syncthreads();

        int jmax = (kt == qt) ? t : 63;
        for (int j = 0; j <= jmax; j++) {
            float s0=0.f, s1=0.f, s2=0.f, s3=0.f;
            const float4* kv = reinterpret_cast<const float4*>(Ks[j]);
            #pragma unroll
            for (int d4 = 0; d4 < DK/4; d4++) {
                float4 kk4 = kv[d4];
                s0 += qr[4*d4  ]*kk4.x;
                s1 += qr[4*d4+1]*kk4.y;
                s2 += qr[4*d4+2]*kk4.z;
                s3 += qr[4*d4+3]*kk4.w;
            }
            float s = ((s0+s1)+(s2+s3)) * 0.125f;

            if (s > m) {
                float corr = __expf(m - s);
                l *= corr;
                #pragma unroll
                for (int d = 0; d < DK; d++) acc[d] *= corr;
                m = s;
            }
            float p = __expf(s - m);
            l += p;
            const float4* vv = reinterpret_cast<const float4*>(Vs[j]);
            #pragma unroll
            for (int d4 = 0; d4 < DK/4; d4++) {
                float4 v4 = vv[d4];
                acc[4*d4  ] += p*v4.x;
                acc[4*d4+1] += p*v4.y;
                acc[4*d4+2] += p*v4.z;
                acc[4*d4+3] += p*v4.w;
            }
        }
    }

    float inv = 1.f / l;
    size_t off = (size_t)(rowbase+qi)*Dm + h*DK;
    #pragma unroll
    for (int d4 = 0; d4 < DK/4; d4++) {
        float v0 = acc[4*d4  ]*inv;
        float v1 = acc[4*d4+1]*inv;
        float v2 = acc[4*d4+2]*inv;
        float v3 = acc[4*d4+3]*inv;
        __nv_bfloat16 h0,l0,h1,l1,h2,l2,h3,l3;
        splitf(v0,h0,l0); splitf(v1,h1,l1); splitf(v2,h2,l2); splitf(v3,h3,l3);
        __nv_bfloat162 p;
        p.x=h0; p.y=h1; *reinterpret_cast<__nv_bfloat162*>(oh+off+4*d4)   = p;
        p.x=h2; p.y=h3; *reinterpret_cast<__nv_bfloat162*>(oh+off+4*d4+2) = p;
        p.x=l0; p.y=l1; *reinterpret_cast<__nv_bfloat162*>(ol+off+4*d4)   = p;
        p.x=l2; p.y=l3; *reinterpret_cast<__nv_bfloat162*>(ol+off+4*d4+2) = p;
    }
}

// ---------------- launch ----------------
extern "C" void kernel_launch(void* const* d_in, const int* in_sizes, int n_in,
                              void* d_out, int out_size) {
    const int*   tokens = (const int*)  d_in[0];
    const float* emb    = (const float*)d_in[1];
    const float* pos    = (const float*)d_in[2];
    const float* Wq     = (const float*)d_in[3];
    const float* bq     = (const float*)d_in[4];
    const float* Wk     = (const float*)d_in[5];
    const float* bk     = (const float*)d_in[6];
    const float* Wv     = (const float*)d_in[7];
    const float* bv     = (const float*)d_in[8];
    const float* Wo     = (const float*)d_in[9];
    const float* bo     = (const float*)d_in[10];
    const float* ln1g   = (const float*)d_in[11];
    const float* ln1b   = (const float*)d_in[12];
    const float* W1     = (const float*)d_in[13];
    const float* b1     = (const float*)d_in[14];
    const float* W2     = (const float*)d_in[15];
    const float* b2     = (const float*)d_in[16];
    const float* ln2g   = (const float*)d_in[17];
    const float* ln2b   = (const float*)d_in[18];
    const float* lnfg   = (const float*)d_in[19];
    const float* lnfb   = (const float*)d_in[20];
    const float* Whead  = (const float*)d_in[21];
    const float* bhead  = (const float*)d_in[22];
    float* out = (float*)d_out;

    float *x, *qkv, *bqkv;
    __nv_bfloat16 *hh,*hl,*oh,*ol,*fh,*fl;
    __nv_bfloat16 *wqkvh,*wqkvl,*woh,*wol,*w1h,*w1l,*w2h,*w2l,*whh,*whl;
    cudaGetSymbolAddress((void**)&x, g_x);
    cudaGetSymbolAddress((void**)&qkv, g_qkv);
    cudaGetSymbolAddress((void**)&bqkv, g_bqkv);
    cudaGetSymbolAddress((void**)&hh, g_hh); cudaGetSymbolAddress((void**)&hl, g_hl);
    cudaGetSymbolAddress((void**)&oh, g_oh); cudaGetSymbolAddress((void**)&ol, g_ol);
    cudaGetSymbolAddress((void**)&fh, g_fh); cudaGetSymbolAddress((void**)&fl, g_fl);
    cudaGetSymbolAddress((void**)&wqkvh, g_wqkvh); cudaGetSymbolAddress((void**)&wqkvl, g_wqkvl);
    cudaGetSymbolAddress((void**)&woh, g_woh); cudaGetSymbolAddress((void**)&wol, g_wol);
    cudaGetSymbolAddress((void**)&w1h, g_w1h); cudaGetSymbolAddress((void**)&w1l, g_w1l);
    cudaGetSymbolAddress((void**)&w2h, g_w2h); cudaGetSymbolAddress((void**)&w2l, g_w2l);
    cudaGetSymbolAddress((void**)&whh, g_whh); cudaGetSymbolAddress((void**)&whl, g_whl);

    // dynamic smem sizes per template config
    const int SM128 = 3 * ((2*128*40 + 2*128*40) * 2);  // 122880
    const int SM64  = 3 * ((2*128*40 + 2*64*40) * 2);   //  92160
    cudaFuncSetAttribute(pgemm<128,0,0>, cudaFuncAttributeMaxDynamicSharedMemorySize, SM128);
    cudaFuncSetAttribute(pgemm<128,1,2>, cudaFuncAttributeMaxDynamicSharedMemorySize, SM128);
    cudaFuncSetAttribute(pgemm<64,0,1>,  cudaFuncAttributeMaxDynamicSharedMemorySize, SM64);

    // split all weights to bf16 hi/lo; QKV packed into [L][1536][512]
    const int TS = 256;
    int nL = Dm*Dm/4;   // one layer of a DxD weight, in float4
    for (int l = 0; l < Lm; l++) {
        split_kernel<<<(nL+TS-1)/TS, TS>>>(Wq + (size_t)l*Dm*Dm, wqkvh + ((size_t)l*NQKV + 0*Dm)*Dm, wqkvl + ((size_t)l*NQKV + 0*Dm)*Dm, nL);
        split_kernel<<<(nL+TS-1)/TS, TS>>>(Wk + (size_t)l*Dm*Dm, wqkvh + ((size_t)l*NQKV + 1*Dm)*Dm, wqkvl + ((size_t)l*NQKV + 1*Dm)*Dm, nL);
        split_kernel<<<(nL+TS-1)/TS, TS>>>(Wv + (size_t)l*Dm*Dm, wqkvh + ((size_t)l*NQKV + 2*Dm)*Dm, wqkvl + ((size_t)l*NQKV + 2*Dm)*Dm, nL);
    }
    pack_bias_kernel<<<(Lm*NQKV+TS-1)/TS, TS>>>(bq, bk, bv, bqkv);
    int nA = Lm*Dm*Dm/4, nF = Lm*DFFm*Dm/4, nH = (int)((size_t)Vv*Dm/4);
    split_kernel<<<(nA+TS-1)/TS, TS>>>(Wo, woh, wol, nA);
    split_kernel<<<(nF+TS-1)/TS, TS>>>(W1, w1h, w1l, nF);
    split_kernel<<<(nF+TS-1)/TS, TS>>>(W2, w2h, w2l, nF);
    split_kernel<<<(nH+TS-1)/TS, TS>>>(Whead, whh, whl, nH);

    embed_kernel<<<(MR*Dm + 255)/256, 256>>>(tokens, emb, pos, x);

    dim3 gQKV(NQKV/128, MR/128);                // (12,16)
    dim3 gN512(Dm/64,   MR/128);                // (8,16)
    dim3 gFF1(DFFm/128, MR/128);                // (16,16)
    dim3 gHead((Vv + 127)/128, MR/128);         // (393,16)
    dim3 gAttn(Sm/64, Bb*Hh);

    for (int l = 0; l < Lm; l++) {
        size_t oQ = (size_t)l*NQKV*Dm, oA = (size_t)l*Dm*Dm;
        size_t oF1 = (size_t)l*DFFm*Dm, oF2 = (size_t)l*Dm*DFFm;

        ln_kernel<<<MR, 128>>>(x, ln1g + l*Dm, ln1b + l*Dm, hh, hl);
        pgemm<128,0,0><<<gQKV,512,SM128>>>(hh, hl, wqkvh+oQ, wqkvl+oQ, bqkv+l*NQKV, nullptr, qkv, nullptr, nullptr, NQKV, Dm);
        attn_kernel<<<gAttn, 64>>>(qkv, oh, ol);
        pgemm<64,0,1><<<gN512,256,SM64>>>(oh, ol, woh+oA, wol+oA, bo+l*Dm, x, x, nullptr, nullptr, Dm, Dm);

        ln_kernel<<<MR, 128>>>(x, ln2g + l*Dm, ln2b + l*Dm, hh, hl);
        pgemm<128,1,2><<<gFF1,512,SM128>>>(hh, hl, w1h+oF1, w1l+oF1, b1+l*DFFm, nullptr, nullptr, fh, fl, DFFm, Dm);
        pgemm<64,0,1><<<gN512,256,SM64>>>(fh, fl, w2h+oF2, w2l+oF2, b2+l*Dm, x, x, nullptr, nullptr, Dm, DFFm);
    }

    ln_kernel<<<MR, 128>>>(x, lnfg, lnfb, hh, hl);
    pgemm<128,0,0><<<gHead,512,SM128>>>(hh, hl, whh, whl, bhead, nullptr, out, nullptr, nullptr, Vv, Dm);
}

// round 6
// speedup vs baseline: 1.7359x; 1.0064x over previous
#include <cuda_runtime.h>
#include <cuda_bf16.h>
#include <math.h>
#include <stdint.h>

#define Dm   512
#define Hh   8
#define DK   64
#define DFFm 2048
#define Lm   4
#define Bb   2
#define Sm   1024
#define Vv   50257
#define MR   (Bb*Sm)   // 2048 rows
#define NQKV (3*Dm)    // 1536

// ---------------- scratch (device globals; no allocs allowed) ----------------
__device__ float g_x[MR*Dm];
__device__ float g_qkv[MR*NQKV];

__device__ __nv_bfloat16 g_hh[MR*Dm],  g_hl[MR*Dm];     // LN output hi/lo
__device__ __nv_bfloat16 g_oh[MR*Dm],  g_ol[MR*Dm];     // attn output hi/lo
__device__ __nv_bfloat16 g_fh[MR*DFFm], g_fl[MR*DFFm];  // FFN1/GELU output hi/lo

__device__ __nv_bfloat16 g_wqkvh[Lm*NQKV*Dm], g_wqkvl[Lm*NQKV*Dm];
__device__ float         g_bqkv[Lm*NQKV];
__device__ __nv_bfloat16 g_woh[Lm*Dm*Dm],   g_wol[Lm*Dm*Dm];
__device__ __nv_bfloat16 g_w1h[Lm*DFFm*Dm], g_w1l[Lm*DFFm*Dm];
__device__ __nv_bfloat16 g_w2h[Lm*Dm*DFFm], g_w2l[Lm*Dm*DFFm];
__device__ __nv_bfloat16 g_whh[(size_t)Vv*Dm], g_whl[(size_t)Vv*Dm];

// ---------------- small helpers ----------------
__device__ __forceinline__ void splitf(float v, __nv_bfloat16& h, __nv_bfloat16& l) {
    h = __float2bfloat16(v);
    l = __float2bfloat16(v - __bfloat162float(h));
}
__device__ __forceinline__ unsigned saddr(const void* p) {
    return (unsigned)__cvta_generic_to_shared(p);
}
__device__ __forceinline__ void ldsm4(unsigned* d, unsigned a) {
    asm volatile("ldmatrix.sync.aligned.m8n8.x4.shared.b16 {%0,%1,%2,%3}, [%4];"
        : "=r"(d[0]), "=r"(d[1]), "=r"(d[2]), "=r"(d[3]) : "r"(a));
}
__device__ __forceinline__ void mma16816(float* c, const unsigned* a, const unsigned* b) {
    asm volatile("mma.sync.aligned.m16n8k16.row.col.f32.bf16.bf16.f32 "
        "{%0,%1,%2,%3}, {%4,%5,%6,%7}, {%8,%9}, {%0,%1,%2,%3};"
        : "+f"(c[0]), "+f"(c[1]), "+f"(c[2]), "+f"(c[3])
        : "r"(a[0]), "r"(a[1]), "r"(a[2]), "r"(a[3]), "r"(b[0]), "r"(b[1]));
}
__device__ __forceinline__ void cp16(uint32_t d, const void* s) {
    asm volatile("cp.async.cg.shared.global [%0], [%1], 16;" :: "r"(d), "l"(s));
}
__device__ __forceinline__ void cp16z(uint32_t d, const void* s, bool ok) {
    int sz = ok ? 16 : 0;
    asm volatile("cp.async.cg.shared.global [%0], [%1], 16, %2;" :: "r"(d), "l"(s), "r"(sz));
}
__device__ __forceinline__ float gelu(float v) {
    return 0.5f * v * (1.0f + erff(v * 0.70710678118654752f));
}

// ---------------- weight split: fp32 -> bf16 hi/lo ----------------
__global__ void split_kernel(const float* __restrict__ s,
                             __nv_bfloat16* __restrict__ h,
                             __nv_bfloat16* __restrict__ l, int n4) {
    int i = blockIdx.x * blockDim.x + threadIdx.x;
    if (i >= n4) return;
    float4 v = reinterpret_cast<const float4*>(s)[i];
    __nv_bfloat16 h0,l0,h1,l1,h2,l2,h3,l3;
    splitf(v.x, h0, l0); splitf(v.y, h1, l1);
    splitf(v.z, h2, l2); splitf(v.w, h3, l3);
    __nv_bfloat162 ph0; ph0.x=h0; ph0.y=h1;
    __nv_bfloat162 ph1; ph1.x=h2; ph1.y=h3;
    __nv_bfloat162 pl0; pl0.x=l0; pl0.y=l1;
    __nv_bfloat162 pl1; pl1.x=l2; pl1.y=l3;
    reinterpret_cast<__nv_bfloat162*>(h)[2*i]   = ph0;
    reinterpret_cast<__nv_bfloat162*>(h)[2*i+1] = ph1;
    reinterpret_cast<__nv_bfloat162*>(l)[2*i]   = pl0;
    reinterpret_cast<__nv_bfloat162*>(l)[2*i+1] = pl1;
}

__global__ void pack_bias_kernel(const float* __restrict__ bq, const float* __restrict__ bk,
                                 const float* __restrict__ bv, float* __restrict__ o) {
    int i = blockIdx.x * blockDim.x + threadIdx.x;
    if (i >= Lm*NQKV) return;
    int l = i / NQKV, c = i % NQKV;
    float v = (c < Dm) ? bq[l*Dm + c] : (c < 2*Dm ? bk[l*Dm + c - Dm] : bv[l*Dm + c - 2*Dm]);
    o[i] = v;
}

// ---------------- embed ----------------
__global__ void embed_kernel(const int* __restrict__ tok,
                             const float* __restrict__ emb,
                             const float* __restrict__ pos,
                             float* __restrict__ x) {
    int idx = blockIdx.x * blockDim.x + threadIdx.x;
    if (idx >= MR*Dm) return;
    int row = idx / Dm, d = idx % Dm;
    int s = row % Sm;
    int t = tok[row];
    x[idx] = emb[t*Dm + d] + pos[s*Dm + d];
}

// ---------------- layernorm -> bf16 hi/lo ----------------
__global__ void __launch_bounds__(128) ln_kernel(const float* __restrict__ x,
                                                 const float* __restrict__ g,
                                                 const float* __restrict__ b,
                                                 __nv_bfloat16* __restrict__ oh,
                                                 __nv_bfloat16* __restrict__ ol) {
    int row = blockIdx.x;
    int t = threadIdx.x;
    const float4 v4 = reinterpret_cast<const float4*>(x + (size_t)row*Dm)[t];
    __shared__ float red[4];

    float s = v4.x + v4.y + v4.z + v4.w;
    #pragma unroll
    for (int o = 16; o > 0; o >>= 1) s += __shfl_xor_sync(0xffffffffu, s, o);
    if ((t & 31) == 0) red[t >> 5] = s;
    __syncthreads();
    float mean = (red[0] + red[1] + red[2] + red[3]) * (1.0f/Dm);
    __syncthreads();

    float dx = v4.x-mean, dy = v4.y-mean, dz = v4.z-mean, dw = v4.w-mean;
    float ss = dx*dx + dy*dy + dz*dz + dw*dw;
    #pragma unroll
    for (int o = 16; o > 0; o >>= 1) ss += __shfl_xor_sync(0xffffffffu, ss, o);
    if ((t & 31) == 0) red[t >> 5] = ss;
    __syncthreads();
    float var = (red[0] + red[1] + red[2] + red[3]) * (1.0f/Dm);
    float inv = rsqrtf(var + 1e-5f);

    float4 gg = reinterpret_cast<const float4*>(g)[t];
    float4 bb = reinterpret_cast<const float4*>(b)[t];
    float o0 = dx*inv*gg.x + bb.x;
    float o1 = dy*inv*gg.y + bb.y;
    float o2 = dz*inv*gg.z + bb.z;
    float o3 = dw*inv*gg.w + bb.w;

    __nv_bfloat16 h0,l0,h1,l1,h2,l2,h3,l3;
    splitf(o0,h0,l0); splitf(o1,h1,l1); splitf(o2,h2,l2); splitf(o3,h3,l3);
    size_t off = (size_t)row*Dm + 4*t;
    __nv_bfloat162 p;
    p.x=h0; p.y=h1; *reinterpret_cast<__nv_bfloat162*>(oh+off)   = p;
    p.x=h2; p.y=h3; *reinterpret_cast<__nv_bfloat162*>(oh+off+2) = p;
    p.x=l0; p.y=l1; *reinterpret_cast<__nv_bfloat162*>(ol+off)   = p;
    p.x=l2; p.y=l3; *reinterpret_cast<__nv_bfloat162*>(ol+off+2) = p;
}

// ---------------- pipelined split-bf16 HMMA GEMM ----------------
// C[M,N] = act(A[M,K] @ W[N,K]^T + bias) ; A=Ah+Al, W=Wh+Wl, 3 MMAs (hh,hl,lh)
// BM=128, BK=32, BN in {64,128}; THREADS=BN*4; 3-stage cp.async pipeline.
// ACT: 0 none, 1 GELU. OUTMODE: 0 fp32 C; 1 fp32 + residual; 2 bf16 hi/lo out.
template<int BN, int ACT, int OUTMODE>
__global__ void __launch_bounds__(BN*4)
pgemm(const __nv_bfloat16* __restrict__ Ah, const __nv_bfloat16* __restrict__ Al,
      const __nv_bfloat16* __restrict__ Wh, const __nv_bfloat16* __restrict__ Wl,
      const float* __restrict__ bias, const float* __restrict__ Rsd,
      float* __restrict__ C, __nv_bfloat16* __restrict__ Ch, __nv_bfloat16* __restrict__ Cl,
      int Nn, int Kn) {
    constexpr int BM = 128, BK = 32;
    constexpr int THREADS = BN*4;
    constexpr int AST = BM*40;                 // halves per A tile (padded stride 40)
    constexpr int WST = BN*40;
    constexpr int OFF_AL = AST*2;              // byte offsets inside a stage
    constexpr int OFF_WH = 2*AST*2;
    constexpr int OFF_WL = (2*AST + WST)*2;
    constexpr int STAGE_B = (2*AST + 2*WST)*2;

    extern __shared__ __align__(16) char smem[];
    uint32_t sb = saddr(smem);

    int tid  = threadIdx.x;
    int lane = tid & 31, warp = tid >> 5;
    int m0 = (warp & 3) * 32;
    int n0 = (warp >> 2) * 32;
    int bm = blockIdx.y * BM;
    int bn = blockIdx.x * BN;
    int nK = Kn / BK;

    float acc[2][4][4];
    #pragma unroll
    for (int i = 0; i < 2; i++)
        #pragma unroll
        for (int j = 0; j < 4; j++)
            #pragma unroll
            for (int r = 0; r < 4; r++) acc[i][j][r] = 0.f;

    auto load_stage = [&](int s, int kt) {
        uint32_t base = sb + s*STAGE_B;
        int k0 = kt*BK;
        #pragma unroll
        for (int i = tid; i < BM*4; i += THREADS) {
            int r = i >> 2, c = (i & 3) << 3;
            uint32_t d = base + (r*40 + c)*2;
            size_t g = (size_t)(bm + r)*Kn + k0 + c;
            cp16(d,          Ah + g);
            cp16(d + OFF_AL, Al + g);
        }
        #pragma unroll
        for (int i = tid; i < BN*4; i += THREADS) {
            int r = i >> 2, c = (i & 3) << 3;
            int gn = bn + r;
            uint32_t d = base + OFF_WH + (r*40 + c)*2;
            size_t g = (size_t)gn*Kn + k0 + c;
            bool ok = gn < Nn;
            cp16z(d,                     Wh + g, ok);
            cp16z(d + (OFF_WL - OFF_WH), Wl + g, ok);
        }
        asm volatile("cp.async.commit_group;" ::: "memory");
    };

    load_stage(0, 0);
    load_stage(1, 1);

    for (int kt = 0; kt < nK; kt++) {
        if (kt == nK - 1) asm volatile("cp.async.wait_group 0;" ::: "memory");
        else              asm volatile("cp.async.wait_group 1;" ::: "memory");
        __syncthreads();
        if (kt + 2 < nK) load_stage((kt + 2) % 3, kt + 2);

        uint32_t base = sb + (kt % 3)*STAGE_B;
        #pragma unroll
        for (int ks = 0; ks < 2; ks++) {
            unsigned ah[2][4], al[2][4], bh[2][4], bl[2][4];
            int ca = ks*16 + ((lane >> 4) << 3);
            #pragma unroll
            for (int i = 0; i < 2; i++) {
                int rw = m0 + i*16 + (lane & 15);
                uint32_t ad = base + (rw*40 + ca)*2;
                ldsm4(ah[i], ad);
                ldsm4(al[i], ad + OFF_AL);
            }
            int cb = ks*16 + (((lane >> 3) & 1) << 3);
            #pragma unroll
            for (int j = 0; j < 2; j++) {
                int rw = n0 + j*16 + ((lane >> 4) << 3) + (lane & 7);
                uint32_t bd = base + OFF_WH + (rw*40 + cb)*2;
                ldsm4(bh[j], bd);
                ldsm4(bl[j], bd + (OFF_WL - OFF_WH));
            }
            #pragma unroll
            for (int i = 0; i < 2; i++)
                #pragma unroll
                for (int jj = 0; jj < 4; jj++) {
                    const unsigned* bfh = &bh[jj >> 1][(jj & 1)*2];
                    const unsigned* bfl = &bl[jj >> 1][(jj & 1)*2];
                    mma16816(acc[i][jj], ah[i], bfh);
                    mma16816(acc[i][jj], ah[i], bfl);
                    mma16816(acc[i][jj], al[i], bfh);
                }
        }
    }

    // epilogue
    bool vecok = ((Nn & 1) == 0) && (bn + BN <= Nn);
    #pragma unroll
    for (int i = 0; i < 2; i++) {
        #pragma unroll
        for (int jj = 0; jj < 4; jj++) {
            int r0 = bm + m0 + i*16 + (lane >> 2);
            int cc = bn + n0 + (jj >> 1)*16 + (jj & 1)*8 + ((lane & 3) << 1);
            #pragma unroll
            for (int hr = 0; hr < 2; hr++) {
                int r = r0 + hr*8;
                float v0 = acc[i][jj][hr*2 + 0];
                float v1 = acc[i][jj][hr*2 + 1];
                if (OUTMODE == 2) {
                    v0 += bias[cc]; v1 += bias[cc+1];
                    if (ACT) { v0 = gelu(v0); v1 = gelu(v1); }
                    __nv_bfloat16 h0,l0,h1,l1;
                    splitf(v0,h0,l0); splitf(v1,h1,l1);
                    __nv_bfloat162 ph; ph.x=h0; ph.y=h1;
                    __nv_bfloat162 pl; pl.x=l0; pl.y=l1;
                    *reinterpret_cast<__nv_bfloat162*>(Ch + (size_t)r*Nn + cc) = ph;
                    *reinterpret_cast<__nv_bfloat162*>(Cl + (size_t)r*Nn + cc) = pl;
                } else if (vecok) {
                    float2 v;
                    v.x = v0 + bias[cc];
                    v.y = v1 + bias[cc+1];
                    if (ACT) { v.x = gelu(v.x); v.y = gelu(v.y); }
                    if (OUTMODE == 1) {
                        float2 r2 = *reinterpret_cast<const float2*>(Rsd + (size_t)r*Nn + cc);
                        v.x += r2.x; v.y += r2.y;
                    }
                    *reinterpret_cast<float2*>(C + (size_t)r*Nn + cc) = v;
                } else {
                    if (cc < Nn) {
                        float v = v0 + bias[cc];
                        if (ACT) v = gelu(v);
                        if (OUTMODE == 1) v += Rsd[(size_t)r*Nn + cc];
                        C[(size_t)r*Nn + cc] = v;
                    }
                    if (cc + 1 < Nn) {
                        float v = v1 + bias[cc+1];
                        if (ACT) v = gelu(v);
                        if (OUTMODE == 1) v += Rsd[(size_t)r*Nn + cc + 1];
                        C[(size_t)r*Nn + cc + 1] = v;
                    }
                }
            }
        }
    }
}

// ---------------- attention: flash-style fp32 over fused qkv buffer ----------------
// qkv layout: [MR][1536]: q at col h*64, k at 512+h*64, v at 1024+h*64
__global__ void __launch_bounds__(64)
attn_kernel(const float* __restrict__ qkv,
            __nv_bfloat16* __restrict__ oh, __nv_bfloat16* __restrict__ ol) {
    int qt = blockIdx.x;
    int bh = blockIdx.y;
    int b = bh / Hh, h = bh % Hh;
    int t = threadIdx.x;
    int qi = qt*64 + t;
    int rowbase = b * Sm;

    __shared__ float Ks[64][DK];
    __shared__ float Vs[64][DK];

    float qr[DK];
    {
        const float4* qp = reinterpret_cast<const float4*>(qkv + (size_t)(rowbase+qi)*NQKV + h*DK);
        #pragma unroll
        for (int d4 = 0; d4 < DK/4; d4++) {
            float4 x = qp[d4];
            qr[4*d4]=x.x; qr[4*d4+1]=x.y; qr[4*d4+2]=x.z; qr[4*d4+3]=x.w;
        }
    }

    float m = -1e30f, l = 0.f;
    float acc[DK];
    #pragma unroll
    for (int d = 0; d < DK; d++) acc[d] = 0.f;

    for (int kt = 0; kt <= qt; kt++) {
        __syncthreads();
        #pragma unroll
        for (int it = 0; it < 16; it++) {
            int r = it*4 + (t >> 4);
            int c = (t & 15) * 4;
            size_t base = (size_t)(rowbase + kt*64 + r)*NQKV + h*DK + c;
            *reinterpret_cast<float4*>(&Ks[r][c]) = *reinterpret_cast<const float4*>(qkv + base + Dm);
            *reinterpret_cast<float4*>(&Vs[r][c]) = *reinterpret_cast<const float4*>(qkv + base + 2*Dm);
        }
        __syncthreads();

        int jmax = (kt == qt) ? t : 63;
        for (int j = 0; j <= jmax; j++) {
            float s0=0.f, s1=0.f, s2=0.f, s3=0.f;
            const float4* kv = reinterpret_cast<const float4*>(Ks[j]);
            #pragma unroll
            for (int d4 = 0; d4 < DK/4; d4++) {
                float4 kk4 = kv[d4];
                s0 += qr[4*d4  ]*kk4.x;
                s1 += qr[4*d4+1]*kk4.y;
                s2 += qr[4*d4+2]*kk4.z;
                s3 += qr[4*d4+3]*kk4.w;
            }
            float s = ((s0+s1)+(s2+s3)) * 0.125f;

            if (s > m) {
                float corr = __expf(m - s);
                l *= corr;
                #pragma unroll
                for (int d = 0; d < DK; d++) acc[d] *= corr;
                m = s;
            }
            float p = __expf(s - m);
            l += p;
            const float4* vv = reinterpret_cast<const float4*>(Vs[j]);
            #pragma unroll
            for (int d4 = 0; d4 < DK/4; d4++) {
                float4 v4 = vv[d4];
                acc[4*d4  ] += p*v4.x;
                acc[4*d4+1] += p*v4.y;
                acc[4*d4+2] += p*v4.z;
                acc[4*d4+3] += p*v4.w;
            }
        }
    }

    float inv = 1.f / l;
    size_t off = (size_t)(rowbase+qi)*Dm + h*DK;
    #pragma unroll
    for (int d4 = 0; d4 < DK/4; d4++) {
        float v0 = acc[4*d4  ]*inv;
        float v1 = acc[4*d4+1]*inv;
        float v2 = acc[4*d4+2]*inv;
        float v3 = acc[4*d4+3]*inv;
        __nv_bfloat16 h0,l0,h1,l1,h2,l2,h3,l3;
        splitf(v0,h0,l0); splitf(v1,h1,l1); splitf(v2,h2,l2); splitf(v3,h3,l3);
        __nv_bfloat162 p;
        p.x=h0; p.y=h1; *reinterpret_cast<__nv_bfloat162*>(oh+off+4*d4)   = p;
        p.x=h2; p.y=h3; *reinterpret_cast<__nv_bfloat162*>(oh+off+4*d4+2) = p;
        p.x=l0; p.y=l1; *reinterpret_cast<__nv_bfloat162*>(ol+off+4*d4)   = p;
        p.x=l2; p.y=l3; *reinterpret_cast<__nv_bfloat162*>(ol+off+4*d4+2) = p;
    }
}

// ---------------- launch ----------------
extern "C" void kernel_launch(void* const* d_in, const int* in_sizes, int n_in,
                              void* d_out, int out_size) {
    const int*   tokens = (const int*)  d_in[0];
    const float* emb    = (const float*)d_in[1];
    const float* pos    = (const float*)d_in[2];
    const float* Wq     = (const float*)d_in[3];
    const float* bq     = (const float*)d_in[4];
    const float* Wk     = (const float*)d_in[5];
    const float* bk     = (const float*)d_in[6];
    const float* Wv     = (const float*)d_in[7];
    const float* bv     = (const float*)d_in[8];
    const float* Wo     = (const float*)d_in[9];
    const float* bo     = (const float*)d_in[10];
    const float* ln1g   = (const float*)d_in[11];
    const float* ln1b   = (const float*)d_in[12];
    const float* W1     = (const float*)d_in[13];
    const float* b1     = (const float*)d_in[14];
    const float* W2     = (const float*)d_in[15];
    const float* b2     = (const float*)d_in[16];
    const float* ln2g   = (const float*)d_in[17];
    const float* ln2b   = (const float*)d_in[18];
    const float* lnfg   = (const float*)d_in[19];
    const float* lnfb   = (const float*)d_in[20];
    const float* Whead  = (const float*)d_in[21];
    const float* bhead  = (const float*)d_in[22];
    float* out = (float*)d_out;

    float *x, *qkv, *bqkv;
    __nv_bfloat16 *hh,*hl,*oh,*ol,*fh,*fl;
    __nv_bfloat16 *wqkvh,*wqkvl,*woh,*wol,*w1h,*w1l,*w2h,*w2l,*whh,*whl;
    cudaGetSymbolAddress((void**)&x, g_x);
    cudaGetSymbolAddress((void**)&qkv, g_qkv);
    cudaGetSymbolAddress((void**)&bqkv, g_bqkv);
    cudaGetSymbolAddress((void**)&hh, g_hh); cudaGetSymbolAddress((void**)&hl, g_hl);
    cudaGetSymbolAddress((void**)&oh, g_oh); cudaGetSymbolAddress((void**)&ol, g_ol);
    cudaGetSymbolAddress((void**)&fh, g_fh); cudaGetSymbolAddress((void**)&fl, g_fl);
    cudaGetSymbolAddress((void**)&wqkvh, g_wqkvh); cudaGetSymbolAddress((void**)&wqkvl, g_wqkvl);
    cudaGetSymbolAddress((void**)&woh, g_woh); cudaGetSymbolAddress((void**)&wol, g_wol);
    cudaGetSymbolAddress((void**)&w1h, g_w1h); cudaGetSymbolAddress((void**)&w1l, g_w1l);
    cudaGetSymbolAddress((void**)&w2h, g_w2h); cudaGetSymbolAddress((void**)&w2l, g_w2l);
    cudaGetSymbolAddress((void**)&whh, g_whh); cudaGetSymbolAddress((void**)&whl, g_whl);

    // dynamic smem sizes per template config
    const int SM128 = 3 * ((2*128*40 + 2*128*40) * 2);  // 122880
    const int SM64  = 3 * ((2*128*40 + 2*64*40) * 2);   //  92160
    cudaFuncSetAttribute(pgemm<128,0,0>, cudaFuncAttributeMaxDynamicSharedMemorySize, SM128);
    cudaFuncSetAttribute(pgemm<128,1,2>, cudaFuncAttributeMaxDynamicSharedMemorySize, SM128);
    cudaFuncSetAttribute(pgemm<64,0,1>,  cudaFuncAttributeMaxDynamicSharedMemorySize, SM64);

    // split all weights to bf16 hi/lo; QKV packed into [L][1536][512]
    const int TS = 256;
    int nL = Dm*Dm/4;   // one layer of a DxD weight, in float4
    for (int l = 0; l < Lm; l++) {
        split_kernel<<<(nL+TS-1)/TS, TS>>>(Wq + (size_t)l*Dm*Dm, wqkvh + ((size_t)l*NQKV + 0*Dm)*Dm, wqkvl + ((size_t)l*NQKV + 0*Dm)*Dm, nL);
        split_kernel<<<(nL+TS-1)/TS, TS>>>(Wk + (size_t)l*Dm*Dm, wqkvh + ((size_t)l*NQKV + 1*Dm)*Dm, wqkvl + ((size_t)l*NQKV + 1*Dm)*Dm, nL);
        split_kernel<<<(nL+TS-1)/TS, TS>>>(Wv + (size_t)l*Dm*Dm, wqkvh + ((size_t)l*NQKV + 2*Dm)*Dm, wqkvl + ((size_t)l*NQKV + 2*Dm)*Dm, nL);
    }
    pack_bias_kernel<<<(Lm*NQKV+TS-1)/TS, TS>>>(bq, bk, bv, bqkv);
    int nA = Lm*Dm*Dm/4, nF = Lm*DFFm*Dm/4, nH = (int)((size_t)Vv*Dm/4);
    split_kernel<<<(nA+TS-1)/TS, TS>>>(Wo, woh, wol, nA);
    split_kernel<<<(nF+TS-1)/TS, TS>>>(W1, w1h, w1l, nF);
    split_kernel<<<(nF+TS-1)/TS, TS>>>(W2, w2h, w2l, nF);
    split_kernel<<<(nH+TS-1)/TS, TS>>>(Whead, whh, whl, nH);

    embed_kernel<<<(MR*Dm + 255)/256, 256>>>(tokens, emb, pos, x);

    dim3 gQKV(NQKV/128, MR/128);                // (12,16)
    dim3 gN512(Dm/64,   MR/128);                // (8,16)
    dim3 gFF1(DFFm/128, MR/128);                // (16,16)
    dim3 gHead((Vv + 127)/128, MR/128);         // (393,16)
    dim3 gAttn(Sm/64, Bb*Hh);

    for (int l = 0; l < Lm; l++) {
        size_t oQ = (size_t)l*NQKV*Dm, oA = (size_t)l*Dm*Dm;
        size_t oF1 = (size_t)l*DFFm*Dm, oF2 = (size_t)l*Dm*DFFm;

        ln_kernel<<<MR, 128>>>(x, ln1g + l*Dm, ln1b + l*Dm, hh, hl);
        pgemm<128,0,0><<<gQKV,512,SM128>>>(hh, hl, wqkvh+oQ, wqkvl+oQ, bqkv+l*NQKV, nullptr, qkv, nullptr, nullptr, NQKV, Dm);
        attn_kernel<<<gAttn, 64>>>(qkv, oh, ol);
        pgemm<64,0,1><<<gN512,256,SM64>>>(oh, ol, woh+oA, wol+oA, bo+l*Dm, x, x, nullptr, nullptr, Dm, Dm);

        ln_kernel<<<MR, 128>>>(x, ln2g + l*Dm, ln2b + l*Dm, hh, hl);
        pgemm<128,1,2><<<gFF1,512,SM128>>>(hh, hl, w1h+oF1, w1l+oF1, b1+l*DFFm, nullptr, nullptr, fh, fl, DFFm, Dm);
        pgemm<64,0,1><<<gN512,256,SM64>>>(fh, fl, w2h+oF2, w2l+oF2, b2+l*Dm, x, x, nullptr, nullptr, Dm, DFFm);
    }

    ln_kernel<<<MR, 128>>>(x, lnfg, lnfb, hh, hl);
    pgemm<128,0,0><<<gHead,512,SM128>>>(hh, hl, whh, whl, bhead, nullptr, out, nullptr, nullptr, Vv, Dm);
}

// round 7
// speedup vs baseline: 2.6601x; 1.5324x over previous
#include <cuda_runtime.h>
#include <cuda_bf16.h>
#include <cuda_fp16.h>
#include <math.h>
#include <stdint.h>

#define Dm   512
#define Hh   8
#define DK   64
#define DFFm 2048
#define Lm   4
#define Bb   2
#define Sm   1024
#define Vv   50257
#define MR   (Bb*Sm)
#define NQKV (3*Dm)

__device__ float g_x[MR*Dm];
__device__ __nv_bfloat16 g_hh[MR*Dm],  g_hl[MR*Dm];
__device__ __nv_bfloat16 g_qkvh[MR*NQKV], g_qkvl[MR*NQKV];
__device__ __nv_bfloat16 g_oh[MR*Dm],  g_ol[MR*Dm];
__device__ __nv_bfloat16 g_fh[MR*DFFm], g_fl[MR*DFFm];

__device__ __nv_bfloat16 g_wqkvh[Lm*NQKV*Dm], g_wqkvl[Lm*NQKV*Dm];
__device__ float         g_bqkv[Lm*NQKV];
__device__ __nv_bfloat16 g_woh[Lm*Dm*Dm],   g_wol[Lm*Dm*Dm];
__device__ __nv_bfloat16 g_w1h[Lm*DFFm*Dm], g_w1l[Lm*DFFm*Dm];
__device__ __nv_bfloat16 g_w2h[Lm*Dm*DFFm], g_w2l[Lm*Dm*DFFm];
__device__ __half        g_whead[(size_t)Vv*Dm];

__device__ __forceinline__ void splitf(float v, __nv_bfloat16& h, __nv_bfloat16& l) {
    h = __float2bfloat16(v);
    l = __float2bfloat16(v - __bfloat162float(h));
}
__device__ __forceinline__ unsigned saddr(const void* p) {
    return (unsigned)__cvta_generic_to_shared(p);
}
__device__ __forceinline__ void ldsm4(unsigned* d, unsigned a) {
    asm volatile("ldmatrix.sync.aligned.m8n8.x4.shared.b16 {%0,%1,%2,%3}, [%4];"
        : "=r"(d[0]), "=r"(d[1]), "=r"(d[2]), "=r"(d[3]) : "r"(a));
}
__device__ __forceinline__ void ldsm4t(unsigned* d, unsigned a) {
    asm volatile("ldmatrix.sync.aligned.m8n8.x4.trans.shared.b16 {%0,%1,%2,%3}, [%4];"
        : "=r"(d[0]), "=r"(d[1]), "=r"(d[2]), "=r"(d[3]) : "r"(a));
}
__device__ __forceinline__ void mma16816(float* c, const unsigned* a, const unsigned* b) {
    asm volatile("mma.sync.aligned.m16n8k16.row.col.f32.bf16.bf16.f32 "
        "{%0,%1,%2,%3}, {%4,%5,%6,%7}, {%8,%9}, {%0,%1,%2,%3};"
        : "+f"(c[0]), "+f"(c[1]), "+f"(c[2]), "+f"(c[3])
        : "r"(a[0]), "r"(a[1]), "r"(a[2]), "r"(a[3]), "r"(b[0]), "r"(b[1]));
}
__device__ __forceinline__ void mma16816h(float* c, const unsigned* a, const unsigned* b) {
    asm volatile("mma.sync.aligned.m16n8k16.row.col.f32.f16.f16.f32 "
        "{%0,%1,%2,%3}, {%4,%5,%6,%7}, {%8,%9}, {%0,%1,%2,%3};"
        : "+f"(c[0]), "+f"(c[1]), "+f"(c[2]), "+f"(c[3])
        : "r"(a[0]), "r"(a[1]), "r"(a[2]), "r"(a[3]), "r"(b[0]), "r"(b[1]));
}
__device__ __forceinline__ void cp16(uint32_t d, const void* s) {
    asm volatile("cp.async.cg.shared.global [%0], [%1], 16;" :: "r"(d), "l"(s));
}
__device__ __forceinline__ void cp16z(uint32_t d, const void* s, bool ok) {
    int sz = ok ? 16 : 0;
    asm volatile("cp.async.cg.shared.global [%0], [%1], 16, %2;" :: "r"(d), "l"(s), "r"(sz));
}
__device__ __forceinline__ float gelu(float v) {
    return 0.5f * v * (1.0f + erff(v * 0.70710678118654752f));
}
__device__ __forceinline__ void packsplit2(float x, float y, unsigned& hi, unsigned& lo) {
    __nv_bfloat16 hx = __float2bfloat16(x), hy = __float2bfloat16(y);
    __nv_bfloat16 lx = __float2bfloat16(x - __bfloat162float(hx));
    __nv_bfloat16 ly = __float2bfloat16(y - __bfloat162float(hy));
    __nv_bfloat162 H; H.x = hx; H.y = hy;
    __nv_bfloat162 L; L.x = lx; L.y = ly;
    hi = *reinterpret_cast<unsigned*>(&H);
    lo = *reinterpret_cast<unsigned*>(&L);
}
__device__ __forceinline__ void store_split4(__nv_bfloat16* dh, __nv_bfloat16* dl, float4 v) {
    __nv_bfloat16 h0,l0,h1,l1,h2,l2,h3,l3;
    splitf(v.x,h0,l0); splitf(v.y,h1,l1); splitf(v.z,h2,l2); splitf(v.w,h3,l3);
    __nv_bfloat162 p;
    p.x=h0; p.y=h1; reinterpret_cast<__nv_bfloat162*>(dh)[0] = p;
    p.x=h2; p.y=h3; reinterpret_cast<__nv_bfloat162*>(dh)[1] = p;
    p.x=l0; p.y=l1; reinterpret_cast<__nv_bfloat162*>(dl)[0] = p;
    p.x=l2; p.y=l3; reinterpret_cast<__nv_bfloat162*>(dl)[1] = p;
}

// fused split of all layer weights
#define WA4    (Dm*Dm/4)
#define QKVTOT (3*Lm*WA4)
#define WOTOT  (Lm*WA4)
#define FTOT   (Lm*DFFm*Dm/4)
#define TOT4   (QKVTOT + WOTOT + 2*FTOT)
__global__ void split_layers_kernel(const float* __restrict__ Wq, const float* __restrict__ Wk,
                                    const float* __restrict__ Wv, const float* __restrict__ Wo,
                                    const float* __restrict__ W1, const float* __restrict__ W2) {
    int idx = blockIdx.x * blockDim.x + threadIdx.x;
    if (idx >= TOT4) return;
    if (idx < QKVTOT) {
        int sect = idx / (Lm*WA4);
        int rem  = idx % (Lm*WA4);
        int l = rem / WA4, e = rem % WA4;
        int r = e / (Dm/4), c4 = e % (Dm/4);
        const float* src = sect == 0 ? Wq : (sect == 1 ? Wk : Wv);
        float4 v = reinterpret_cast<const float4*>(src)[(size_t)l*WA4 + e];
        size_t d4 = ((size_t)l*NQKV + sect*Dm + r)*(Dm/4) + c4;
        store_split4(g_wqkvh + d4*4, g_wqkvl + d4*4, v);
    } else if (idx < QKVTOT + WOTOT) {
        int e = idx - QKVTOT;
        float4 v = reinterpret_cast<const float4*>(Wo)[e];
        store_split4(g_woh + (size_t)e*4, g_wol + (size_t)e*4, v);
    } else if (idx < QKVTOT + WOTOT + FTOT) {
        int e = idx - QKVTOT - WOTOT;
        float4 v = reinterpret_cast<const float4*>(W1)[e];
        store_split4(g_w1h + (size_t)e*4, g_w1l + (size_t)e*4, v);
    } else {
        int e = idx - QKVTOT - WOTOT - FTOT;
        float4 v = reinterpret_cast<const float4*>(W2)[e];
        store_split4(g_w2h + (size_t)e*4, g_w2l + (size_t)e*4, v);
    }
}

__global__ void split_head_kernel(const float* __restrict__ W) {
    size_t idx = (size_t)blockIdx.x * blockDim.x + threadIdx.x;
    size_t n4 = (size_t)Vv*Dm/4;
    if (idx >= n4) return;
    float4 v = reinterpret_cast<const float4*>(W)[idx];
    __half2 a, b;
    a.x = __float2half_rn(v.x); a.y = __float2half_rn(v.y);
    b.x = __float2half_rn(v.z); b.y = __float2half_rn(v.w);
    reinterpret_cast<__half2*>(g_whead)[2*idx]   = a;
    reinterpret_cast<__half2*>(g_whead)[2*idx+1] = b;
}

__global__ void pack_bias_kernel(const float* __restrict__ bq, const float* __restrict__ bk,
                                 const float* __restrict__ bv) {
    int i = blockIdx.x * blockDim.x + threadIdx.x;
    if (i >= Lm*NQKV) return;
    int l = i / NQKV, c = i % NQKV;
    g_bqkv[i] = (c < Dm) ? bq[l*Dm + c] : (c < 2*Dm ? bk[l*Dm + c - Dm] : bv[l*Dm + c - 2*Dm]);
}

__global__ void embed_kernel(const int* __restrict__ tok, const float* __restrict__ emb,
                             const float* __restrict__ pos, float* __restrict__ x) {
    int idx = blockIdx.x * blockDim.x + threadIdx.x;
    if (idx >= MR*Dm) return;
    int row = idx / Dm, d = idx % Dm;
    x[idx] = emb[tok[row]*Dm + d] + pos[(row % Sm)*Dm + d];
}

// LN -> 16-bit hi/lo (bf16, or fp16 when mode16)
__global__ void __launch_bounds__(128) ln_kernel(const float* __restrict__ x,
                                                 const float* __restrict__ g,
                                                 const float* __restrict__ b,
                                                 __nv_bfloat16* __restrict__ oh,
                                                 __nv_bfloat16* __restrict__ ol, int mode16) {
    int row = blockIdx.x, t = threadIdx.x;
    const float4 v4 = reinterpret_cast<const float4*>(x + (size_t)row*Dm)[t];
    __shared__ float red[4];
    float s = v4.x + v4.y + v4.z + v4.w;
    #pragma unroll
    for (int o = 16; o > 0; o >>= 1) s += __shfl_xor_sync(0xffffffffu, s, o);
    if ((t & 31) == 0) red[t >> 5] = s;
    __syncthreads();
    float mean = (red[0]+red[1]+red[2]+red[3]) * (1.0f/Dm);
    __syncthreads();
    float dx = v4.x-mean, dy = v4.y-mean, dz = v4.z-mean, dw = v4.w-mean;
    float ss = dx*dx + dy*dy + dz*dz + dw*dw;
    #pragma unroll
    for (int o = 16; o > 0; o >>= 1) ss += __shfl_xor_sync(0xffffffffu, ss, o);
    if ((t & 31) == 0) red[t >> 5] = ss;
    __syncthreads();
    float inv = rsqrtf((red[0]+red[1]+red[2]+red[3])*(1.0f/Dm) + 1e-5f);
    float4 gg = reinterpret_cast<const float4*>(g)[t];
    float4 bb = reinterpret_cast<const float4*>(b)[t];
    float o0 = dx*inv*gg.x + bb.x, o1 = dy*inv*gg.y + bb.y;
    float o2 = dz*inv*gg.z + bb.z, o3 = dw*inv*gg.w + bb.w;
    size_t off = (size_t)row*Dm + 4*t;
    if (mode16) {
        __half* hp = reinterpret_cast<__half*>(oh);
        __half* lp = reinterpret_cast<__half*>(ol);
        __half h0=__float2half_rn(o0), h1=__float2half_rn(o1), h2=__float2half_rn(o2), h3=__float2half_rn(o3);
        __half L0=__float2half_rn(o0-__half2float(h0)), L1=__float2half_rn(o1-__half2float(h1));
        __half L2=__float2half_rn(o2-__half2float(h2)), L3=__float2half_rn(o3-__half2float(h3));
        __half2 p;
        p.x=h0; p.y=h1; *reinterpret_cast<__half2*>(hp+off)   = p;
        p.x=h2; p.y=h3; *reinterpret_cast<__half2*>(hp+off+2) = p;
        p.x=L0; p.y=L1; *reinterpret_cast<__half2*>(lp+off)   = p;
        p.x=L2; p.y=L3; *reinterpret_cast<__half2*>(lp+off+2) = p;
    } else {
        __nv_bfloat16 h0,l0,h1,l1,h2,l2,h3,l3;
        splitf(o0,h0,l0); splitf(o1,h1,l1); splitf(o2,h2,l2); splitf(o3,h3,l3);
        __nv_bfloat162 p;
        p.x=h0; p.y=h1; *reinterpret_cast<__nv_bfloat162*>(oh+off)   = p;
        p.x=h2; p.y=h3; *reinterpret_cast<__nv_bfloat162*>(oh+off+2) = p;
        p.x=l0; p.y=l1; *reinterpret_cast<__nv_bfloat162*>(ol+off)   = p;
        p.x=l2; p.y=l3; *reinterpret_cast<__nv_bfloat162*>(ol+off+2) = p;
    }
}

// pipelined split HMMA GEMM. FP16=0: bf16 3-MMA; FP16=1: fp16 A-split x single fp16 W
template<int BN, int ACT, int OUTMODE, int FP16>
__global__ void __launch_bounds__(BN*4)
pgemm(const __nv_bfloat16* __restrict__ Ah, const __nv_bfloat16* __restrict__ Al,
      const __nv_bfloat16* __restrict__ Wh, const __nv_bfloat16* __restrict__ Wl,
      const float* __restrict__ bias, const float* __restrict__ Rsd,
      float* __restrict__ C, __nv_bfloat16* __restrict__ Ch, __nv_bfloat16* __restrict__ Cl,
      int Nn, int Kn) {
    constexpr int BM = 128, BK = 32;
    constexpr int THREADS = BN*4;
    constexpr int AST = BM*40, WST = BN*40;
    constexpr int OFF_AL = AST*2, OFF_WH = 2*AST*2, OFF_WL = (2*AST + WST)*2;
    constexpr int STAGE_B = (2*AST + 2*WST)*2;

    extern __shared__ __align__(16) char smem[];
    uint32_t sb = saddr(smem);
    int tid = threadIdx.x, lane = tid & 31, warp = tid >> 5;
    int m0 = (warp & 3)*32, n0 = (warp >> 2)*32;

    int gx = gridDim.x, gy = gridDim.y;
    int bid = blockIdx.y * gx + blockIdx.x;
    const int GM = 8;
    int gsz = GM * gx;
    int grp = bid / gsz, rem = bid % gsz;
    int gmr = (gy - grp*GM < GM) ? (gy - grp*GM) : GM;
    int bm = (grp*GM + rem % gmr) * BM;
    int bn = (rem / gmr) * BN;
    int nK = Kn / BK;

    float acc[2][4][4];
    #pragma unroll
    for (int i = 0; i < 2; i++)
        #pragma unroll
        for (int j = 0; j < 4; j++)
            #pragma unroll
            for (int r = 0; r < 4; r++) acc[i][j][r] = 0.f;

    auto load_stage = [&](int s, int kt) {
        uint32_t base = sb + s*STAGE_B;
        int k0 = kt*BK;
        #pragma unroll
        for (int i = tid; i < BM*4; i += THREADS) {
            int r = i >> 2, c = (i & 3) << 3;
            uint32_t d = base + (r*40 + c)*2;
            size_t g = (size_t)(bm + r)*Kn + k0 + c;
            cp16(d, Ah + g);
            cp16(d + OFF_AL, Al + g);
        }
        #pragma unroll
        for (int i = tid; i < BN*4; i += THREADS) {
            int r = i >> 2, c = (i & 3) << 3;
            int gn = bn + r;
            uint32_t d = base + OFF_WH + (r*40 + c)*2;
            size_t g = (size_t)gn*Kn + k0 + c;
            bool ok = gn < Nn;
            cp16z(d, Wh + g, ok);
            if (!FP16) cp16z(d + (OFF_WL - OFF_WH), Wl + g, ok);
        }
        asm volatile("cp.async.commit_group;" ::: "memory");
    };

    load_stage(0, 0);
    load_stage(1, 1);

    for (int kt = 0; kt < nK; kt++) {
        if (kt == nK - 1) asm volatile("cp.async.wait_group 0;" ::: "memory");
        else              asm volatile("cp.async.wait_group 1;" ::: "memory");
        __syncthreads();
        if (kt + 2 < nK) load_stage((kt + 2) % 3, kt + 2);

        uint32_t base = sb + (kt % 3)*STAGE_B;
        #pragma unroll
        for (int ks = 0; ks < 2; ks++) {
            unsigned ah[2][4], al[2][4], bh[2][4], bl[2][4];
            int ca = ks*16 + ((lane >> 4) << 3);
            #pragma unroll
            for (int i = 0; i < 2; i++) {
                int rw = m0 + i*16 + (lane & 15);
                uint32_t ad = base + (rw*40 + ca)*2;
                ldsm4(ah[i], ad);
                ldsm4(al[i], ad + OFF_AL);
            }
            int cb = ks*16 + (((lane >> 3) & 1) << 3);
            #pragma unroll
            for (int j = 0; j < 2; j++) {
                int rw = n0 + j*16 + ((lane >> 4) << 3) + (lane & 7);
                uint32_t bd = base + OFF_WH + (rw*40 + cb)*2;
                ldsm4(bh[j], bd);
                if (!FP16) ldsm4(bl[j], bd + (OFF_WL - OFF_WH));
            }
            #pragma unroll
            for (int i = 0; i < 2; i++)
                #pragma unroll
                for (int jj = 0; jj < 4; jj++) {
                    const unsigned* bfh = &bh[jj >> 1][(jj & 1)*2];
                    if (FP16) {
                        mma16816h(acc[i][jj], ah[i], bfh);
                        mma16816h(acc[i][jj], al[i], bfh);
                    } else {
                        const unsigned* bfl = &bl[jj >> 1][(jj & 1)*2];
                        mma16816(acc[i][jj], ah[i], bfh);
                        mma16816(acc[i][jj], ah[i], bfl);
                        mma16816(acc[i][jj], al[i], bfh);
                    }
                }
        }
    }

    bool vecok = ((Nn & 1) == 0) && (bn + BN <= Nn);
    #pragma unroll
    for (int i = 0; i < 2; i++) {
        #pragma unroll
        for (int jj = 0; jj < 4; jj++) {
            int r0 = bm + m0 + i*16 + (lane >> 2);
            int cc = bn + n0 + (jj >> 1)*16 + (jj & 1)*8 + ((lane & 3) << 1);
            #pragma unroll
            for (int hr = 0; hr < 2; hr++) {
                int r = r0 + hr*8;
                float v0 = acc[i][jj][hr*2+0], v1 = acc[i][jj][hr*2+1];
                if (OUTMODE == 2) {
                    v0 += bias[cc]; v1 += bias[cc+1];
                    if (ACT) { v0 = gelu(v0); v1 = gelu(v1); }
                    unsigned ph, pl;
                    packsplit2(v0, v1, ph, pl);
                    *reinterpret_cast<unsigned*>(Ch + (size_t)r*Nn + cc) = ph;
                    *reinterpret_cast<unsigned*>(Cl + (size_t)r*Nn + cc) = pl;
                } else if (vecok) {
                    float2 v;
                    v.x = v0 + bias[cc]; v.y = v1 + bias[cc+1];
                    if (ACT) { v.x = gelu(v.x); v.y = gelu(v.y); }
                    if (OUTMODE == 1) {
                        float2 r2 = *reinterpret_cast<const float2*>(Rsd + (size_t)r*Nn + cc);
                        v.x += r2.x; v.y += r2.y;
                    }
                    *reinterpret_cast<float2*>(C + (size_t)r*Nn + cc) = v;
                } else {
                    if (cc < Nn) {
                        float v = v0 + bias[cc];
                        if (ACT) v = gelu(v);
                        if (OUTMODE == 1) v += Rsd[(size_t)r*Nn + cc];
                        C[(size_t)r*Nn + cc] = v;
                    }
                    if (cc + 1 < Nn) {
                        float v = v1 + bias[cc+1];
                        if (ACT) v = gelu(v);
                        if (OUTMODE == 1) v += Rsd[(size_t)r*Nn + cc + 1];
                        C[(size_t)r*Nn + cc + 1] = v;
                    }
                }
            }
        }
    }
}

// tensor-core flash attention: block=(qt, b*8+h), 128 thr = 4 warps (16 q-rows each)
#define AT_SMEM 92160
__global__ void __launch_bounds__(128)
attn_kernel(const __nv_bfloat16* __restrict__ qkvh, const __nv_bfloat16* __restrict__ qkvl,
            __nv_bfloat16* __restrict__ oh, __nv_bfloat16* __restrict__ ol) {
    extern __shared__ __align__(16) char sm[];
    uint32_t sb = saddr(sm);
    int qt = blockIdx.x, bh = blockIdx.y;
    int b = bh >> 3, h = bh & 7;
    int tid = threadIdx.x, lane = tid & 31, w = tid >> 5;
    int tokbase = b * Sm;
    const int QL_B = 9216, ST0 = 18432, ST_SZ = 36864;
    // stage: KH+0 KL+9216 VH+18432 VL+27648; rows padded to 144B

    #pragma unroll
    for (int t = 0; t < 4; t++) {
        int i = tid + t*128;
        int r = i >> 3, c8 = i & 7;
        uint32_t off = r*144 + c8*16;
        size_t g = (size_t)(tokbase + qt*64 + r)*NQKV + h*DK + c8*8;
        cp16(sb + off,        qkvh + g);
        cp16(sb + QL_B + off, qkvl + g);
    }
    {
        uint32_t base = sb + ST0;
        #pragma unroll
        for (int t = 0; t < 4; t++) {
            int i = tid + t*128;
            int r = i >> 3, c8 = i & 7;
            uint32_t off = r*144 + c8*16;
            size_t g = (size_t)(tokbase + r)*NQKV + h*DK + c8*8;
            cp16(base + off,         qkvh + g + Dm);
            cp16(base + 9216 + off,  qkvl + g + Dm);
            cp16(base + 18432 + off, qkvh + g + 2*Dm);
            cp16(base + 27648 + off, qkvl + g + 2*Dm);
        }
    }
    asm volatile("cp.async.commit_group;" ::: "memory");

    unsigned qfh[4][4], qfl[4][4];
    float ao[8][4];
    #pragma unroll
    for (int d = 0; d < 8; d++)
        #pragma unroll
        for (int t = 0; t < 4; t++) ao[d][t] = 0.f;
    float m0 = -1e30f, m1 = -1e30f, l0 = 0.f, l1 = 0.f;

    for (int kt = 0; kt <= qt; kt++) {
        asm volatile("cp.async.wait_group 0;" ::: "memory");
        __syncthreads();
        if (kt == 0) {
            #pragma unroll
            for (int ks = 0; ks < 4; ks++) {
                uint32_t a = sb + (w*16 + (lane & 15))*144 + (ks*16 + ((lane >> 4) << 3))*2;
                ldsm4(qfh[ks], a);
                ldsm4(qfl[ks], a + QL_B);
            }
        }
        if (kt < qt) {
            uint32_t base = sb + ST0 + ((kt+1) & 1)*ST_SZ;
            #pragma unroll
            for (int t = 0; t < 4; t++) {
                int i = tid + t*128;
                int r = i >> 3, c8 = i & 7;
                uint32_t off = r*144 + c8*16;
                size_t g = (size_t)(tokbase + (kt+1)*64 + r)*NQKV + h*DK + c8*8;
                cp16(base + off,         qkvh + g + Dm);
                cp16(base + 9216 + off,  qkvl + g + Dm);
                cp16(base + 18432 + off, qkvh + g + 2*Dm);
                cp16(base + 27648 + off, qkvl + g + 2*Dm);
            }
            asm volatile("cp.async.commit_group;" ::: "memory");
        }
        uint32_t kb = sb + ST0 + (kt & 1)*ST_SZ;

        float sc[8][4];
        #pragma unroll
        for (int j = 0; j < 8; j++)
            #pragma unroll
            for (int t = 0; t < 4; t++) sc[j][t] = 0.f;

        #pragma unroll
        for (int ks = 0; ks < 4; ks++) {
            unsigned kh[4][4], kl[4][4];
            #pragma unroll
            for (int jp = 0; jp < 4; jp++) {
                uint32_t a = kb + (jp*16 + ((lane >> 4) << 3) + (lane & 7))*144
                           + (ks*16 + (((lane >> 3) & 1) << 3))*2;
                ldsm4(kh[jp], a);
                ldsm4(kl[jp], a + 9216);
            }
            #pragma unroll
            for (int jp = 0; jp < 4; jp++)
                #pragma unroll
                for (int sub = 0; sub < 2; sub++) {
                    int j = jp*2 + sub;
                    mma16816(sc[j], qfh[ks], &kh[jp][sub*2]);
                    mma16816(sc[j], qfh[ks], &kl[jp][sub*2]);
                    mma16816(sc[j], qfl[ks], &kh[jp][sub*2]);
                }
        }

        int rg = qt*64 + w*16 + (lane >> 2);
        #pragma unroll
        for (int j = 0; j < 8; j++)
            #pragma unroll
            for (int t = 0; t < 4; t++) sc[j][t] *= 0.125f;
        if (kt == qt) {
            #pragma unroll
            for (int j = 0; j < 8; j++) {
                int cg = kt*64 + j*8 + ((lane & 3) << 1);
                if (cg     > rg)     sc[j][0] = -1e30f;
                if (cg + 1 > rg)     sc[j][1] = -1e30f;
                if (cg     > rg + 8) sc[j][2] = -1e30f;
                if (cg + 1 > rg + 8) sc[j][3] = -1e30f;
            }
        }

        float mx0 = -1e30f, mx1 = -1e30f;
        #pragma unroll
        for (int j = 0; j < 8; j++) {
            mx0 = fmaxf(mx0, fmaxf(sc[j][0], sc[j][1]));
            mx1 = fmaxf(mx1, fmaxf(sc[j][2], sc[j][3]));
        }
        mx0 = fmaxf(mx0, __shfl_xor_sync(0xffffffffu, mx0, 1));
        mx0 = fmaxf(mx0, __shfl_xor_sync(0xffffffffu, mx0, 2));
        mx1 = fmaxf(mx1, __shfl_xor_sync(0xffffffffu, mx1, 1));
        mx1 = fmaxf(mx1, __shfl_xor_sync(0xffffffffu, mx1, 2));
        float nm0 = fmaxf(m0, mx0), nm1 = fmaxf(m1, mx1);
        float c0 = __expf(m0 - nm0), c1 = __expf(m1 - nm1);
        m0 = nm0; m1 = nm1;
        float s0 = 0.f, s1 = 0.f;
        #pragma unroll
        for (int j = 0; j < 8; j++) {
            sc[j][0] = __expf(sc[j][0] - m0);
            sc[j][1] = __expf(sc[j][1] - m0);
            sc[j][2] = __expf(sc[j][2] - m1);
            sc[j][3] = __expf(sc[j][3] - m1);
            s0 += sc[j][0] + sc[j][1];
            s1 += sc[j][2] + sc[j][3];
        }
        l0 = l0*c0 + s0;
        l1 = l1*c1 + s1;
        #pragma unroll
        for (int d = 0; d < 8; d++) {
            ao[d][0] *= c0; ao[d][1] *= c0;
            ao[d][2] *= c1; ao[d][3] *= c1;
        }

        unsigned ph[4][4], pl[4][4];
        #pragma unroll
        for (int kp = 0; kp < 4; kp++) {
            int j0 = 2*kp, j1 = 2*kp + 1;
            packsplit2(sc[j0][0], sc[j0][1], ph[kp][0], pl[kp][0]);
            packsplit2(sc[j0][2], sc[j0][3], ph[kp][1], pl[kp][1]);
            packsplit2(sc[j1][0], sc[j1][1], ph[kp][2], pl[kp][2]);
            packsplit2(sc[j1][2], sc[j1][3], ph[kp][3], pl[kp][3]);
        }

        #pragma unroll
        for (int kp = 0; kp < 4; kp++) {
            unsigned vh[4][4], vl[4][4];
            #pragma unroll
            for (int dp = 0; dp < 4; dp++) {
                uint32_t a = kb + 18432 + (kp*16 + (((lane >> 3) & 1) << 3) + (lane & 7))*144
                           + (dp*16 + ((lane >> 4) << 3))*2;
                ldsm4t(vh[dp], a);
                ldsm4t(vl[dp], a + 9216);
            }
            #pragma unroll
            for (int dp = 0; dp < 4; dp++)
                #pragma unroll
                for (int sub = 0; sub < 2; sub++) {
                    int d = dp*2 + sub;
                    mma16816(ao[d], ph[kp], &vh[dp][sub*2]);
                    mma16816(ao[d], ph[kp], &vl[dp][sub*2]);
                    mma16816(ao[d], pl[kp], &vh[dp][sub*2]);
                }
        }
    }

    l0 += __shfl_xor_sync(0xffffffffu, l0, 1);
    l0 += __shfl_xor_sync(0xffffffffu, l0, 2);
    l1 += __shfl_xor_sync(0xffffffffu, l1, 1);
    l1 += __shfl_xor_sync(0xffffffffu, l1, 2);
    float i0 = 1.f / l0, i1 = 1.f / l1;
    int row0 = tokbase + qt*64 + w*16 + (lane >> 2);
    #pragma unroll
    for (int d = 0; d < 8; d++) {
        int col = h*DK + d*8 + ((lane & 3) << 1);
        unsigned phv, plv;
        packsplit2(ao[d][0]*i0, ao[d][1]*i0, phv, plv);
        *reinterpret_cast<unsigned*>(oh + (size_t)row0*Dm + col) = phv;
        *reinterpret_cast<unsigned*>(ol + (size_t)row0*Dm + col) = plv;
        packsplit2(ao[d][2]*i1, ao[d][3]*i1, phv, plv);
        *reinterpret_cast<unsigned*>(oh + (size_t)(row0+8)*Dm + col) = phv;
        *reinterpret_cast<unsigned*>(ol + (size_t)(row0+8)*Dm + col) = plv;
    }
}

extern "C" void kernel_launch(void* const* d_in, const int* in_sizes, int n_in,
                              void* d_out, int out_size) {
    const int*   tokens = (const int*)  d_in[0];
    const float* emb    = (const float*)d_in[1];
    const float* pos    = (const float*)d_in[2];
    const float* Wq     = (const float*)d_in[3];
    const float* bq     = (const float*)d_in[4];
    const float* Wk     = (const float*)d_in[5];
    const float* bk     = (const float*)d_in[6];
    const float* Wv     = (const float*)d_in[7];
    const float* bv     = (const float*)d_in[8];
    const float* Wo     = (const float*)d_in[9];
    const float* bo     = (const float*)d_in[10];
    const float* ln1g   = (const float*)d_in[11];
    const float* ln1b   = (const float*)d_in[12];
    const float* W1     = (const float*)d_in[13];
    const float* b1     = (const float*)d_in[14];
    const float* W2     = (const float*)d_in[15];
    const float* b2     = (const float*)d_in[16];
    const float* ln2g   = (const float*)d_in[17];
    const float* ln2b   = (const float*)d_in[18];
    const float* lnfg   = (const float*)d_in[19];
    const float* lnfb   = (const float*)d_in[20];
    const float* Whead  = (const float*)d_in[21];
    const float* bhead  = (const float*)d_in[22];
    float* out = (float*)d_out;

    float *x, *bqkv;
    __nv_bfloat16 *hh,*hl,*qh,*ql,*ohp,*olp,*fh,*fl;
    __nv_bfloat16 *wqkvh,*wqkvl,*woh,*wol,*w1h,*w1l,*w2h,*w2l;
    __half *whead;
    cudaGetSymbolAddress((void**)&x, g_x);
    cudaGetSymbolAddress((void**)&bqkv, g_bqkv);
    cudaGetSymbolAddress((void**)&hh, g_hh);   cudaGetSymbolAddress((void**)&hl, g_hl);
    cudaGetSymbolAddress((void**)&qh, g_qkvh); cudaGetSymbolAddress((void**)&ql, g_qkvl);
    cudaGetSymbolAddress((void**)&ohp, g_oh);  cudaGetSymbolAddress((void**)&olp, g_ol);
    cudaGetSymbolAddress((void**)&fh, g_fh);   cudaGetSymbolAddress((void**)&fl, g_fl);
    cudaGetSymbolAddress((void**)&wqkvh, g_wqkvh); cudaGetSymbolAddress((void**)&wqkvl, g_wqkvl);
    cudaGetSymbolAddress((void**)&woh, g_woh); cudaGetSymbolAddress((void**)&wol, g_wol);
    cudaGetSymbolAddress((void**)&w1h, g_w1h); cudaGetSymbolAddress((void**)&w1l, g_w1l);
    cudaGetSymbolAddress((void**)&w2h, g_w2h); cudaGetSymbolAddress((void**)&w2l, g_w2l);
    cudaGetSymbolAddress((void**)&whead, g_whead);

    const int SM128 = 3 * ((2*128*40 + 2*128*40) * 2);
    const int SM64  = 3 * ((2*128*40 + 2*64*40) * 2);
    cudaFuncSetAttribute(pgemm<128,0,2,0>, cudaFuncAttributeMaxDynamicSharedMemorySize, SM128);
    cudaFuncSetAttribute(pgemm<128,1,2,0>, cudaFuncAttributeMaxDynamicSharedMemorySize, SM128);
    cudaFuncSetAttribute(pgemm<64,0,1,0>,  cudaFuncAttributeMaxDynamicSharedMemorySize, SM64);
    cudaFuncSetAttribute(pgemm<128,0,0,1>, cudaFuncAttributeMaxDynamicSharedMemorySize, SM128);
    cudaFuncSetAttribute(attn_kernel, cudaFuncAttributeMaxDynamicSharedMemorySize, AT_SMEM);

    const int TS = 256;
    split_layers_kernel<<<(TOT4+TS-1)/TS, TS>>>(Wq, Wk, Wv, Wo, W1, W2);
    split_head_kernel<<<(int)(((size_t)Vv*Dm/4 + TS-1)/TS), TS>>>(Whead);
    pack_bias_kernel<<<(Lm*NQKV+TS-1)/TS, TS>>>(bq, bk, bv);
    embed_kernel<<<(MR*Dm + 255)/256, 256>>>(tokens, emb, pos, x);

    dim3 gQKV(NQKV/128, MR/128);
    dim3 gN512(Dm/64,   MR/128);
    dim3 gFF1(DFFm/128, MR/128);
    dim3 gHead((Vv + 127)/128, MR/128);
    dim3 gAttn(Sm/64, Bb*Hh);

    for (int l = 0; l < Lm; l++) {
        size_t oQ = (size_t)l*NQKV*Dm, oA = (size_t)l*Dm*Dm;
        size_t oF1 = (size_t)l*DFFm*Dm, oF2 = (size_t)l*Dm*DFFm;

        ln_kernel<<<MR, 128>>>(x, ln1g + l*Dm, ln1b + l*Dm, hh, hl, 0);
        pgemm<128,0,2,0><<<gQKV,512,SM128>>>(hh, hl, wqkvh+oQ, wqkvl+oQ, bqkv+l*NQKV, nullptr, nullptr, qh, ql, NQKV, Dm);
        attn_kernel<<<gAttn, 128, AT_SMEM>>>(qh, ql, ohp, olp);
        pgemm<64,0,1,0><<<gN512,256,SM64>>>(ohp, olp, woh+oA, wol+oA, bo+l*Dm, x, x, nullptr, nullptr, Dm, Dm);

        ln_kernel<<<MR, 128>>>(x, ln2g + l*Dm, ln2b + l*Dm, hh, hl, 0);
        pgemm<128,1,2,0><<<gFF1,512,SM128>>>(hh, hl, w1h+oF1, w1l+oF1, b1+l*DFFm, nullptr, nullptr, fh, fl, DFFm, Dm);
        pgemm<64,0,1,0><<<gN512,256,SM64>>>(fh, fl, w2h+oF2, w2l+oF2, b2+l*Dm, x, x, nullptr, nullptr, Dm, DFFm);
    }

    ln_kernel<<<MR, 128>>>(x, lnfg, lnfb, hh, hl, 1);
    pgemm<128,0,0,1><<<gHead,512,SM128>>>(hh, hl, (const __nv_bfloat16*)whead, nullptr,
                                          bhead, nullptr, out, nullptr, nullptr, Vv, Dm);
}